// round 2
// baseline (speedup 1.0000x reference)
#include <cuda_runtime.h>
#include <cuda_bf16.h>

// ---------------------------------------------------------------------------
// GAT layer, fp32 baseline.
//   h   [8,2048,128] f32
//   adj [8,2048,2048] i32 (0/1)
//   W   [128,128] f32  (out_dim, in_dim)
//   a   [256] f32      (a_src = a[0:128], a_dst = a[128:256])
//   out [8,2048,128] f32
//
// out[b,i,:] = sum_j adj * exp(lrelu(s_i + t_j)) * Wh[b,j,:] / Z_i   (0 if Z==0)
// ---------------------------------------------------------------------------

#define BATCH 8
#define NNODE 2048
#define DIM   128
#define NROWS (BATCH * NNODE)   // 16384

__device__ float g_Wh[NROWS * DIM];   // 8 MB scratch
__device__ float g_s[NROWS];
__device__ float g_t[NROWS];

// ---------------------------------------------------------------------------
// Kernel 1: Wh = h @ W^T.  Block = 256 threads computes 32 rows x 128 dims.
// ---------------------------------------------------------------------------
__global__ __launch_bounds__(256) void gat_wh_kernel(
    const float* __restrict__ h, const float* __restrict__ W)
{
    __shared__ float sh_w[128][65];   // [dim][f-chunk], pad 65 for conflict-free
    __shared__ float sh_h[32][65];    // [row][f-chunk]

    const int tid = threadIdx.x;
    const int tx  = tid & 31;         // dim group: dims {tx, tx+32, tx+64, tx+96}
    const int ty  = tid >> 5;         // row group: rows {ty, ty+8, ty+16, ty+24}
    const int row0 = blockIdx.x * 32;

    float acc[4][4];
#pragma unroll
    for (int m = 0; m < 4; m++)
#pragma unroll
        for (int k = 0; k < 4; k++) acc[m][k] = 0.f;

    for (int f0 = 0; f0 < 128; f0 += 64) {
        __syncthreads();
        // load W chunk: 128 dims x 64 f
        for (int k = tid; k < 128 * 64; k += 256) {
            int d = k >> 6, f = k & 63;
            sh_w[d][f] = W[d * 128 + f0 + f];
        }
        // load h chunk: 32 rows x 64 f
        for (int k = tid; k < 32 * 64; k += 256) {
            int r = k >> 6, f = k & 63;
            sh_h[r][f] = h[(row0 + r) * 128 + f0 + f];
        }
        __syncthreads();

#pragma unroll 8
        for (int f = 0; f < 64; ++f) {
            float hv[4], wv[4];
#pragma unroll
            for (int m = 0; m < 4; m++) hv[m] = sh_h[ty + 8 * m][f];
#pragma unroll
            for (int k = 0; k < 4; k++) wv[k] = sh_w[tx + 32 * k][f];
#pragma unroll
            for (int m = 0; m < 4; m++)
#pragma unroll
                for (int k = 0; k < 4; k++) acc[m][k] += hv[m] * wv[k];
        }
    }

#pragma unroll
    for (int m = 0; m < 4; m++)
#pragma unroll
        for (int k = 0; k < 4; k++)
            g_Wh[(row0 + ty + 8 * m) * DIM + tx + 32 * k] = acc[m][k];
}

// ---------------------------------------------------------------------------
// Kernel 1b: s = Wh @ a_src, t = Wh @ a_dst.  One warp per row.
// ---------------------------------------------------------------------------
__global__ __launch_bounds__(256) void gat_st_kernel(const float* __restrict__ a)
{
    const int row  = blockIdx.x * 8 + (threadIdx.x >> 5);
    const int lane = threadIdx.x & 31;

    float4 wv = ((const float4*)(g_Wh + (size_t)row * DIM))[lane];
    float4 as = ((const float4*)a)[lane];
    float4 ad = ((const float4*)a)[lane + 32];

    float sv = wv.x * as.x + wv.y * as.y + wv.z * as.z + wv.w * as.w;
    float tv = wv.x * ad.x + wv.y * ad.y + wv.z * ad.z + wv.w * ad.w;

#pragma unroll
    for (int o = 16; o > 0; o >>= 1) {
        sv += __shfl_down_sync(0xFFFFFFFFu, sv, o);
        tv += __shfl_down_sync(0xFFFFFFFFu, tv, o);
    }
    if (lane == 0) { g_s[row] = sv; g_t[row] = tv; }
}

// ---------------------------------------------------------------------------
// Kernel 2: fused masked-softmax aggregation (no max shift needed; scores
// are bounded). Block = 512 threads = 16 warps = 16 rows; j tiled by 64.
// ---------------------------------------------------------------------------
#define TI 16
#define TJ 64

__global__ __launch_bounds__(512) void gat_attn_kernel(
    const int* __restrict__ adj, float* __restrict__ out)
{
    __shared__ float sh_wh[TJ][DIM];   // 32 KB
    __shared__ float sh_t[TJ];
    __shared__ int   sh_adj[TI][TJ];   // 4 KB

    const int b    = blockIdx.y;
    const int i0   = blockIdx.x * TI;
    const int warp = threadIdx.x >> 5;      // row within tile
    const int lane = threadIdx.x & 31;      // 4 dims: 4*lane .. 4*lane+3
    const int i    = i0 + warp;

    const float s_i = g_s[b * NNODE + i];
    const float* WhB = g_Wh + (size_t)b * NNODE * DIM;
    const int*   adjT = adj + ((size_t)b * NNODE + i0) * NNODE;

    float4 acc = make_float4(0.f, 0.f, 0.f, 0.f);
    float  Z   = 0.f;

    for (int j0 = 0; j0 < NNODE; j0 += TJ) {
        __syncthreads();
        // stage Wh tile (TJ x 128 floats = 2048 float4)
        {
            const float4* src = (const float4*)(WhB + j0 * DIM);
            float4* dst = (float4*)&sh_wh[0][0];
            for (int k = threadIdx.x; k < TJ * (DIM / 4); k += 512)
                dst[k] = src[k];
        }
        // stage t chunk
        if (threadIdx.x < TJ)
            sh_t[threadIdx.x] = g_t[b * NNODE + j0 + threadIdx.x];
        // stage adj tile (TI x TJ ints)
        for (int k = threadIdx.x; k < TI * TJ; k += 512) {
            int r = k / TJ, c = k % TJ;
            sh_adj[r][c] = adjT[(size_t)r * NNODE + j0 + c];
        }
        __syncthreads();

#pragma unroll 4
        for (int jj = 0; jj < TJ; ++jj) {
            if (sh_adj[warp][jj]) {              // warp-uniform branch
                float e = s_i + sh_t[jj];
                e = e > 0.f ? e : 0.2f * e;
                float w = __expf(e);
                Z += w;
                float4 v = *(const float4*)&sh_wh[jj][lane * 4];
                acc.x += w * v.x;
                acc.y += w * v.y;
                acc.z += w * v.z;
                acc.w += w * v.w;
            }
        }
    }

    const float inv = (Z > 0.f) ? (1.f / Z) : 0.f;
    float4 o = make_float4(acc.x * inv, acc.y * inv, acc.z * inv, acc.w * inv);
    *(float4*)(out + ((size_t)b * NNODE + i) * DIM + lane * 4) = o;
}

// ---------------------------------------------------------------------------
extern "C" void kernel_launch(void* const* d_in, const int* in_sizes, int n_in,
                              void* d_out, int out_size)
{
    const float* h   = (const float*)d_in[0];
    const int*   adj = (const int*)  d_in[1];
    const float* W   = (const float*)d_in[2];
    const float* a   = (const float*)d_in[3];
    float*       out = (float*)d_out;

    gat_wh_kernel<<<NROWS / 32, 256>>>(h, W);
    gat_st_kernel<<<NROWS / 8, 256>>>(a);

    dim3 grid(NNODE / TI, BATCH);
    gat_attn_kernel<<<grid, 512>>>(adj, out);
}

// round 4
// speedup vs baseline: 4.4620x; 4.4620x over previous
#include <cuda_runtime.h>
#include <cuda_fp16.h>
#include <cstdint>

#define BATCH 8
#define NNODE 2048
#define DIM   128
#define NROWS (BATCH * NNODE)

__device__ float g_Wh[NROWS * DIM];                 // 8 MB fp32 Wh
__device__ float g_u[NROWS], g_v[NROWS], g_p[NROWS], g_q[NROWS];
__device__ __half g_BH[NROWS * DIM];                // Wh hi fp16, [b][j][f]
__device__ __half g_BL[NROWS * DIM];                // Wh lo fp16

// ---------------- helpers ----------------
__device__ __forceinline__ uint32_t smem_u32(const void* p) {
    uint32_t a;
    asm("{ .reg .u64 t; cvta.to.shared.u64 t, %1; cvt.u32.u64 %0, t; }" : "=r"(a) : "l"(p));
    return a;
}
__device__ __forceinline__ void ldsm_x4(uint32_t& r0, uint32_t& r1, uint32_t& r2, uint32_t& r3, uint32_t a) {
    asm volatile("ldmatrix.sync.aligned.m8n8.x4.shared.b16 {%0,%1,%2,%3}, [%4];"
                 : "=r"(r0), "=r"(r1), "=r"(r2), "=r"(r3) : "r"(a));
}
__device__ __forceinline__ void ldsm_x4t(uint32_t& r0, uint32_t& r1, uint32_t& r2, uint32_t& r3, uint32_t a) {
    asm volatile("ldmatrix.sync.aligned.m8n8.x4.trans.shared.b16 {%0,%1,%2,%3}, [%4];"
                 : "=r"(r0), "=r"(r1), "=r"(r2), "=r"(r3) : "r"(a));
}
__device__ __forceinline__ void mma16816(float* c, const uint32_t* a, uint32_t b0, uint32_t b1) {
    asm volatile(
        "mma.sync.aligned.m16n8k16.row.col.f32.f16.f16.f32 "
        "{%0,%1,%2,%3}, {%4,%5,%6,%7}, {%8,%9}, {%0,%1,%2,%3};"
        : "+f"(c[0]), "+f"(c[1]), "+f"(c[2]), "+f"(c[3])
        : "r"(a[0]), "r"(a[1]), "r"(a[2]), "r"(a[3]), "r"(b0), "r"(b1));
}
__device__ __forceinline__ void cp_async16(uint32_t dst, const void* src) {
    asm volatile("cp.async.cg.shared.global [%0], [%1], 16;" :: "r"(dst), "l"(src));
}
__device__ __forceinline__ uint32_t pack_f16x2(float lo, float hi) {   // lower<-lo, upper<-hi
    uint32_t r;
    asm("cvt.rn.f16x2.f32 %0, %1, %2;" : "=r"(r) : "f"(hi), "f"(lo));
    return r;
}
#define SWA(o) ((o) ^ (((o) >> 3) & 0x70))   // swizzle for 128B rows
#define SWB(o) ((o) ^ (((o) >> 4) & 0x70))   // swizzle for 256B rows

// ---------------------------------------------------------------------------
// K1: Wh = h @ W^T (fp32)
// ---------------------------------------------------------------------------
__global__ __launch_bounds__(256) void gat_wh_kernel(
    const float* __restrict__ h, const float* __restrict__ W)
{
    __shared__ float sh_w[128][65];
    __shared__ float sh_h[32][65];
    const int tid = threadIdx.x, tx = tid & 31, ty = tid >> 5;
    const int row0 = blockIdx.x * 32;

    float acc[4][4];
#pragma unroll
    for (int m = 0; m < 4; m++)
#pragma unroll
        for (int k = 0; k < 4; k++) acc[m][k] = 0.f;

    for (int f0 = 0; f0 < 128; f0 += 64) {
        __syncthreads();
        for (int k = tid; k < 128 * 64; k += 256)
            sh_w[k >> 6][k & 63] = W[(k >> 6) * 128 + f0 + (k & 63)];
        for (int k = tid; k < 32 * 64; k += 256)
            sh_h[k >> 6][k & 63] = h[(row0 + (k >> 6)) * 128 + f0 + (k & 63)];
        __syncthreads();
#pragma unroll 8
        for (int f = 0; f < 64; ++f) {
            float hv[4], wv[4];
#pragma unroll
            for (int m = 0; m < 4; m++) hv[m] = sh_h[ty + 8 * m][f];
#pragma unroll
            for (int k = 0; k < 4; k++) wv[k] = sh_w[tx + 32 * k][f];
#pragma unroll
            for (int m = 0; m < 4; m++)
#pragma unroll
                for (int k = 0; k < 4; k++) acc[m][k] += hv[m] * wv[k];
        }
    }
#pragma unroll
    for (int m = 0; m < 4; m++)
#pragma unroll
        for (int k = 0; k < 4; k++)
            g_Wh[(row0 + ty + 8 * m) * DIM + tx + 32 * k] = acc[m][k];
}

// ---------------------------------------------------------------------------
// K2: per-node factors u=e^s, p=e^.2s, v=e^t, q=e^.2t
// ---------------------------------------------------------------------------
__global__ __launch_bounds__(256) void gat_st_kernel(const float* __restrict__ a)
{
    const int row = blockIdx.x * 8 + (threadIdx.x >> 5);
    const int lane = threadIdx.x & 31;
    float4 wv = ((const float4*)(g_Wh + (size_t)row * DIM))[lane];
    float4 as = ((const float4*)a)[lane];
    float4 ad = ((const float4*)a)[lane + 32];
    float sv = wv.x * as.x + wv.y * as.y + wv.z * as.z + wv.w * as.w;
    float tv = wv.x * ad.x + wv.y * ad.y + wv.z * ad.z + wv.w * ad.w;
#pragma unroll
    for (int o = 16; o > 0; o >>= 1) {
        sv += __shfl_down_sync(0xFFFFFFFFu, sv, o);
        tv += __shfl_down_sync(0xFFFFFFFFu, tv, o);
    }
    if (lane == 0) {
        g_u[row] = __expf(sv);   g_p[row] = __expf(0.2f * sv);
        g_v[row] = __expf(tv);   g_q[row] = __expf(0.2f * tv);
    }
}

// ---------------------------------------------------------------------------
// K3: split Wh into fp16 hi/lo (same row-major layout, no transpose)
// ---------------------------------------------------------------------------
__global__ __launch_bounds__(256) void gat_split_kernel()
{
    const int idx = blockIdx.x * 256 + threadIdx.x;     // float4 index
    float4 w = ((const float4*)g_Wh)[idx];
    uint32_t b0 = __float_as_uint(w.x), b1 = __float_as_uint(w.y);
    uint32_t b2 = __float_as_uint(w.z), b3 = __float_as_uint(w.w);
    float h0 = __uint_as_float(b0 & 0xFFFFE000u), h1 = __uint_as_float(b1 & 0xFFFFE000u);
    float h2 = __uint_as_float(b2 & 0xFFFFE000u), h3 = __uint_as_float(b3 & 0xFFFFE000u);
    uint2 hi = make_uint2(pack_f16x2(h0, h1), pack_f16x2(h2, h3));
    uint2 lo = make_uint2(pack_f16x2(w.x - h0, w.y - h1), pack_f16x2(w.z - h2, w.w - h3));
    ((uint2*)g_BH)[idx] = hi;
    ((uint2*)g_BL)[idx] = lo;
}

// ---------------------------------------------------------------------------
// K4: fused P-construction + mma.sync GEMM + normalize epilogue
// ---------------------------------------------------------------------------
#define TK 64
#define SM_AH(b)  ((b) * 16384)             // P hi  (128 x 64 fp16, 128B rows)
#define SM_AL(b)  (32768 + (b) * 16384)     // P lo
#define SM_BH2(b) (65536 + (b) * 16384)     // Wh hi (64 x 128 fp16, 256B rows)
#define SM_BL2(b) (98304 + (b) * 16384)     // Wh lo
#define SM_ADJ(b) (131072 + (b) * 32768)    // adj   (128 x 64 int)
#define SM_ZR     196608
#define SM_ZI     197120
#define SMEM_SZ   197632

__global__ void __launch_bounds__(256, 1) gat_fused(
    const int* __restrict__ adj, float* __restrict__ out)
{
    extern __shared__ char sm[];
    const uint32_t sb = smem_u32(sm);
    const int tid = threadIdx.x, lane = tid & 31, wid = tid >> 5;
    const int b = blockIdx.y, i0 = blockIdx.x * 128;
    const int tx = tid & 15, ty = tid >> 4;

    const int* adjB = adj + ((size_t)(b * NNODE + i0)) * NNODE;
    const __half* BHg = g_BH + (size_t)b * NNODE * DIM;
    const __half* BLg = g_BL + (size_t)b * NNODE * DIM;

    float u_r[8], p_r[8];
#pragma unroll
    for (int m = 0; m < 8; m++) {
        int i = b * NNODE + i0 + ty + 16 * m;
        u_r[m] = g_u[i];  p_r[m] = g_p[i];
    }

    // prologue: stream tile 0 (B hi/lo + adj) into buffer 0
#pragma unroll
    for (int c2 = 0; c2 < 4; c2++) {
        int c = tid + 256 * c2;
        int row = c >> 4, col = c & 15;
        uint32_t sw = SWB((uint32_t)(row * 256 + col * 16));
        cp_async16(sb + SM_BH2(0) + sw, BHg + (size_t)row * DIM + col * 8);
        cp_async16(sb + SM_BL2(0) + sw, BLg + (size_t)row * DIM + col * 8);
    }
#pragma unroll
    for (int c2 = 0; c2 < 8; c2++) {
        int c = tid + 256 * c2;
        int row = c >> 4, col = c & 15;
        cp_async16(sb + SM_ADJ(0) + (uint32_t)(row * 256 + col * 16),
                   adjB + (size_t)row * NNODE + col * 4);
    }
    asm volatile("cp.async.commit_group;" ::: "memory");

    float4 vN = *(const float4*)(g_v + b * NNODE + 4 * tx);
    float4 qN = *(const float4*)(g_q + b * NNODE + 4 * tx);

    float acc[4][4][4];
#pragma unroll
    for (int mt = 0; mt < 4; mt++)
#pragma unroll
        for (int nt = 0; nt < 4; nt++)
#pragma unroll
            for (int e = 0; e < 4; e++) acc[mt][nt][e] = 0.f;
    float zacc[8] = {0.f, 0.f, 0.f, 0.f, 0.f, 0.f, 0.f, 0.f};

    const int warpM = wid >> 2, warpN = wid & 3;
    const int l15 = lane & 15, l16 = lane >> 4;
    const uint32_t xorv = (uint32_t)((l15 & 7) << 4);
    uint32_t aRowOff[4];
#pragma unroll
    for (int mt = 0; mt < 4; mt++)
        aRowOff[mt] = (uint32_t)((warpM * 64 + mt * 16 + l15) * 128);
    uint32_t bColOff[2];
#pragma unroll
    for (int ng = 0; ng < 2; ng++)
        bColOff[ng] = ((uint32_t)((warpN * 32 + ng * 16 + l16 * 8) * 2)) ^ xorv;
    const uint32_t bRow0 = (uint32_t)(l15 * 256);
    const uint32_t aCol0 = (uint32_t)(l16 * 16);

    for (int kt = 0; kt < NNODE / TK; ++kt) {
        const int buf = kt & 1, nbuf = buf ^ 1;

        asm volatile("cp.async.wait_group 0;" ::: "memory");
        __syncthreads();   // tile kt resident; all warps done with mma(kt-1)

        // stream tile kt+1
        if (kt < 31) {
            const int j1 = (kt + 1) * TK;
#pragma unroll
            for (int c2 = 0; c2 < 4; c2++) {
                int c = tid + 256 * c2;
                int row = c >> 4, col = c & 15;
                uint32_t sw = SWB((uint32_t)(row * 256 + col * 16));
                cp_async16(sb + SM_BH2(nbuf) + sw, BHg + (size_t)(j1 + row) * DIM + col * 8);
                cp_async16(sb + SM_BL2(nbuf) + sw, BLg + (size_t)(j1 + row) * DIM + col * 8);
            }
#pragma unroll
            for (int c2 = 0; c2 < 8; c2++) {
                int c = tid + 256 * c2;
                int row = c >> 4, col = c & 15;
                cp_async16(sb + SM_ADJ(nbuf) + (uint32_t)(row * 256 + col * 16),
                           adjB + (size_t)row * NNODE + j1 + col * 4);
            }
        }
        asm volatile("cp.async.commit_group;" ::: "memory");

        // construct P(kt): w = max(u*v, p*q) & -adj ; split into fp16 hi/lo
        float4 vC = vN, qC = qN;
        if (kt < 31) {
            vN = *(const float4*)(g_v + b * NNODE + (kt + 1) * TK + 4 * tx);
            qN = *(const float4*)(g_q + b * NNODE + (kt + 1) * TK + 4 * tx);
        }
#pragma unroll
        for (int m = 0; m < 8; m++) {
            const int row = ty + 16 * m;
            int4 a4 = *(const int4*)(sm + SM_ADJ(buf) + row * 256 + tx * 16);
            const float u = u_r[m], p = p_r[m];
            uint32_t w0 = __float_as_uint(fmaxf(u * vC.x, p * qC.x)) & (uint32_t)(-a4.x);
            uint32_t w1 = __float_as_uint(fmaxf(u * vC.y, p * qC.y)) & (uint32_t)(-a4.y);
            uint32_t w2 = __float_as_uint(fmaxf(u * vC.z, p * qC.z)) & (uint32_t)(-a4.z);
            uint32_t w3 = __float_as_uint(fmaxf(u * vC.w, p * qC.w)) & (uint32_t)(-a4.w);
            float f0 = __uint_as_float(w0), f1 = __uint_as_float(w1);
            float f2 = __uint_as_float(w2), f3 = __uint_as_float(w3);
            zacc[m] += (f0 + f1) + (f2 + f3);
            float h0 = __uint_as_float(w0 & 0xFFFFE000u), h1 = __uint_as_float(w1 & 0xFFFFE000u);
            float h2 = __uint_as_float(w2 & 0xFFFFE000u), h3 = __uint_as_float(w3 & 0xFFFFE000u);
            uint32_t sw = SWA((uint32_t)(row * 128 + tx * 8));
            *(uint2*)(sm + SM_AH(buf) + sw) =
                make_uint2(pack_f16x2(h0, h1), pack_f16x2(h2, h3));
            *(uint2*)(sm + SM_AL(buf) + sw) =
                make_uint2(pack_f16x2(f0 - h0, f1 - h1), pack_f16x2(f2 - h2, f3 - h3));
        }
        __syncthreads();   // P(kt) visible

        // mma over tile kt
        const uint32_t AH = sb + SM_AH(buf), AL = sb + SM_AL(buf);
        const uint32_t BH = sb + SM_BH2(buf), BL = sb + SM_BL2(buf);
#pragma unroll
        for (int kk = 0; kk < 4; ++kk) {
            const uint32_t aCol = ((uint32_t)(kk * 32) + aCol0) ^ xorv;
            uint32_t aH[4][4], aL[4][4];
#pragma unroll
            for (int mt = 0; mt < 4; mt++) {
                ldsm_x4(aH[mt][0], aH[mt][1], aH[mt][2], aH[mt][3], AH + aRowOff[mt] + aCol);
                ldsm_x4(aL[mt][0], aL[mt][1], aL[mt][2], aL[mt][3], AL + aRowOff[mt] + aCol);
            }
            const uint32_t bRow = bRow0 + (uint32_t)(kk * 4096);
            uint32_t bH[2][4], bLr[2][4];
#pragma unroll
            for (int ng = 0; ng < 2; ng++) {
                ldsm_x4t(bH[ng][0], bH[ng][1], bH[ng][2], bH[ng][3], BH + bRow + bColOff[ng]);
                ldsm_x4t(bLr[ng][0], bLr[ng][1], bLr[ng][2], bLr[ng][3], BL + bRow + bColOff[ng]);
            }
#pragma unroll
            for (int mt = 0; mt < 4; mt++)
#pragma unroll
                for (int nt = 0; nt < 4; nt++) {
                    const int g = nt >> 1, h = (nt & 1) * 2;
                    mma16816(acc[mt][nt], aH[mt], bH[g][h], bH[g][h + 1]);
                    mma16816(acc[mt][nt], aH[mt], bLr[g][h], bLr[g][h + 1]);
                    mma16816(acc[mt][nt], aL[mt], bH[g][h], bH[g][h + 1]);
                }
        }
    }

    // Z reduction across the 16 threads sharing each row
    float* zr = (float*)(sm + SM_ZR);
    float* zi = (float*)(sm + SM_ZI);
#pragma unroll
    for (int m = 0; m < 8; m++) {
        float z = zacc[m];
#pragma unroll
        for (int o = 1; o < 16; o <<= 1)
            z += __shfl_xor_sync(0xFFFFFFFFu, z, o);
        if (tx == 0) zr[ty + 16 * m] = z;
    }
    __syncthreads();
    if (tid < 128) {
        float z = zr[tid];
        zi[tid] = (z > 0.f) ? (1.f / z) : 0.f;
    }
    __syncthreads();

    // write normalized output
    float* outB = out + ((size_t)(b * NNODE + i0)) * DIM;
#pragma unroll
    for (int mt = 0; mt < 4; mt++) {
        const int r0 = warpM * 64 + mt * 16 + (lane >> 2);
        const int r1 = r0 + 8;
        const float z0 = zi[r0], z1 = zi[r1];
#pragma unroll
        for (int nt = 0; nt < 4; nt++) {
            const int c0 = warpN * 32 + nt * 8 + (lane & 3) * 2;
            *(float2*)(outB + (size_t)r0 * DIM + c0) =
                make_float2(acc[mt][nt][0] * z0, acc[mt][nt][1] * z0);
            *(float2*)(outB + (size_t)r1 * DIM + c0) =
                make_float2(acc[mt][nt][2] * z1, acc[mt][nt][3] * z1);
        }
    }
}

// ---------------------------------------------------------------------------
extern "C" void kernel_launch(void* const* d_in, const int* in_sizes, int n_in,
                              void* d_out, int out_size)
{
    const float* h   = (const float*)d_in[0];
    const int*   adj = (const int*)  d_in[1];
    const float* W   = (const float*)d_in[2];
    const float* a   = (const float*)d_in[3];
    float*       out = (float*)d_out;

    static int smem_set = 0;
    if (!smem_set) {
        cudaFuncSetAttribute(gat_fused, cudaFuncAttributeMaxDynamicSharedMemorySize, SMEM_SZ);
        smem_set = 1;
    }

    gat_wh_kernel<<<NROWS / 32, 256>>>(h, W);
    gat_st_kernel<<<NROWS / 8, 256>>>(a);
    gat_split_kernel<<<NROWS * DIM / 4 / 256, 256>>>();
    gat_fused<<<dim3(NNODE / 128, BATCH), 256, SMEM_SZ>>>(adj, out);
}

// round 5
// speedup vs baseline: 5.7434x; 1.2872x over previous
#include <cuda_runtime.h>
#include <cuda_fp16.h>
#include <cstdint>

#define BATCH 8
#define NNODE 2048
#define DIM   128
#define NROWS (BATCH * NNODE)

__device__ float  g_u[NROWS], g_v[NROWS], g_p[NROWS], g_q[NROWS];
__device__ __half g_BH[NROWS * DIM];     // Wh hi fp16 [b][j][f]
__device__ __half g_BL[NROWS * DIM];     // Wh lo fp16
__device__ __half g_WTH[DIM * DIM];      // W^T hi fp16 [f][o]
__device__ __half g_WTL[DIM * DIM];      // W^T lo fp16

// ---------------- helpers ----------------
__device__ __forceinline__ uint32_t smem_u32(const void* p) {
    uint32_t a;
    asm("{ .reg .u64 t; cvta.to.shared.u64 t, %1; cvt.u32.u64 %0, t; }" : "=r"(a) : "l"(p));
    return a;
}
__device__ __forceinline__ void ldsm_x4(uint32_t& r0, uint32_t& r1, uint32_t& r2, uint32_t& r3, uint32_t a) {
    asm volatile("ldmatrix.sync.aligned.m8n8.x4.shared.b16 {%0,%1,%2,%3}, [%4];"
                 : "=r"(r0), "=r"(r1), "=r"(r2), "=r"(r3) : "r"(a));
}
__device__ __forceinline__ void ldsm_x4t(uint32_t& r0, uint32_t& r1, uint32_t& r2, uint32_t& r3, uint32_t a) {
    asm volatile("ldmatrix.sync.aligned.m8n8.x4.trans.shared.b16 {%0,%1,%2,%3}, [%4];"
                 : "=r"(r0), "=r"(r1), "=r"(r2), "=r"(r3) : "r"(a));
}
__device__ __forceinline__ void mma16816(float* c, const uint32_t* a, uint32_t b0, uint32_t b1) {
    asm volatile(
        "mma.sync.aligned.m16n8k16.row.col.f32.f16.f16.f32 "
        "{%0,%1,%2,%3}, {%4,%5,%6,%7}, {%8,%9}, {%0,%1,%2,%3};"
        : "+f"(c[0]), "+f"(c[1]), "+f"(c[2]), "+f"(c[3])
        : "r"(a[0]), "r"(a[1]), "r"(a[2]), "r"(a[3]), "r"(b0), "r"(b1));
}
__device__ __forceinline__ void cp_async16(uint32_t dst, const void* src) {
    asm volatile("cp.async.cg.shared.global [%0], [%1], 16;" :: "r"(dst), "l"(src));
}
__device__ __forceinline__ uint32_t pack_f16x2(float lo, float hi) {   // lower<-lo, upper<-hi
    uint32_t r;
    asm("cvt.rn.f16x2.f32 %0, %1, %2;" : "=r"(r) : "f"(hi), "f"(lo));
    return r;
}
#define SWA(o) ((o) ^ (((o) >> 3) & 0x70))   // 128B rows
#define SWB(o) ((o) ^ (((o) >> 4) & 0x70))   // 256B rows

// ---------------------------------------------------------------------------
// K0: W -> W^T hi/lo fp16
// ---------------------------------------------------------------------------
__global__ __launch_bounds__(256) void gat_wprep(const float* __restrict__ W)
{
    const int idx = blockIdx.x * 256 + threadIdx.x;   // 0..16383
    const int o = idx >> 7, f = idx & 127;
    float w = W[idx];
    __half hi = __float2half_rn(w);
    float lo = w - __half2float(hi);
    g_WTH[f * 128 + o] = hi;
    g_WTL[f * 128 + o] = __float2half_rn(lo);
}

// ---------------------------------------------------------------------------
// K1: Wh = h @ W^T via mma.sync, hi/lo fp16, writes g_BH/g_BL directly.
//     CTA = 128 rows x 128 cols, K=128. 1 wave of 128 CTAs.
// ---------------------------------------------------------------------------
#define K1_AH 0
#define K1_AL 32768
#define K1_BH 65536
#define K1_BL 98304
#define K1_SMEM 131072

__global__ void __launch_bounds__(256, 1) gat_wh_mma(const float* __restrict__ h)
{
    extern __shared__ char sm[];
    const uint32_t sb = smem_u32(sm);
    const int tid = threadIdx.x, lane = tid & 31, wid = tid >> 5;
    const int row0 = blockIdx.x * 128;

    // W^T hi/lo -> smem (256B rows, SWB)
#pragma unroll
    for (int c = 0; c < 8; c++) {
        int idx = tid + 256 * c;
        int r = idx >> 4, col = idx & 15;
        uint32_t sw = (uint32_t)(r * 256 + ((col * 16) ^ ((r & 7) << 4)));
        cp_async16(sb + K1_BH + sw, g_WTH + r * 128 + col * 8);
        cp_async16(sb + K1_BL + sw, g_WTL + r * 128 + col * 8);
    }
    asm volatile("cp.async.commit_group;" ::: "memory");

    // h tile fp32 -> hi/lo fp16 smem (256B rows, SWB)
#pragma unroll
    for (int c = 0; c < 16; c++) {
        int idx = tid + 256 * c;
        int r = idx >> 5, fq = idx & 31;
        float4 w = *(const float4*)(h + (size_t)(row0 + r) * 128 + fq * 4);
        __half h0 = __float2half_rn(w.x), h1 = __float2half_rn(w.y);
        __half h2 = __float2half_rn(w.z), h3 = __float2half_rn(w.w);
        float l0 = w.x - __half2float(h0), l1 = w.y - __half2float(h1);
        float l2 = w.z - __half2float(h2), l3 = w.w - __half2float(h3);
        uint32_t sw = (uint32_t)(r * 256 + ((fq * 8) ^ ((r & 7) << 4)));
        __half2 hA = __halves2half2(h0, h1), hB = __halves2half2(h2, h3);
        *(uint2*)(sm + K1_AH + sw) =
            make_uint2(*(uint32_t*)&hA, *(uint32_t*)&hB);
        *(uint2*)(sm + K1_AL + sw) =
            make_uint2(pack_f16x2(l0, l1), pack_f16x2(l2, l3));
    }
    asm volatile("cp.async.wait_group 0;" ::: "memory");
    __syncthreads();

    const int warpM = wid >> 2, warpN = wid & 3;
    const int l15 = lane & 15, l16 = lane >> 4;
    const uint32_t xorv = (uint32_t)((l15 & 7) << 4);

    float acc[4][4][4];
#pragma unroll
    for (int mt = 0; mt < 4; mt++)
#pragma unroll
        for (int nt = 0; nt < 4; nt++)
#pragma unroll
            for (int e = 0; e < 4; e++) acc[mt][nt][e] = 0.f;

    uint32_t aRow[4];
#pragma unroll
    for (int mt = 0; mt < 4; mt++)
        aRow[mt] = (uint32_t)((warpM * 64 + mt * 16 + l15) * 256);
    uint32_t bCol[2];
#pragma unroll
    for (int ng = 0; ng < 2; ng++)
        bCol[ng] = ((uint32_t)((warpN * 32 + ng * 16 + l16 * 8) * 2)) ^ xorv;

#pragma unroll
    for (int kk = 0; kk < 8; kk++) {
        const uint32_t aCol = ((uint32_t)(kk * 32 + l16 * 16)) ^ xorv;
        uint32_t aH[4][4], aL[4][4];
#pragma unroll
        for (int mt = 0; mt < 4; mt++) {
            ldsm_x4(aH[mt][0], aH[mt][1], aH[mt][2], aH[mt][3], sb + K1_AH + aRow[mt] + aCol);
            ldsm_x4(aL[mt][0], aL[mt][1], aL[mt][2], aL[mt][3], sb + K1_AL + aRow[mt] + aCol);
        }
        const uint32_t bRow = (uint32_t)((kk * 16 + l15) * 256);
        uint32_t bH[2][4], bL[2][4];
#pragma unroll
        for (int ng = 0; ng < 2; ng++) {
            ldsm_x4t(bH[ng][0], bH[ng][1], bH[ng][2], bH[ng][3], sb + K1_BH + bRow + bCol[ng]);
            ldsm_x4t(bL[ng][0], bL[ng][1], bL[ng][2], bL[ng][3], sb + K1_BL + bRow + bCol[ng]);
        }
#pragma unroll
        for (int mt = 0; mt < 4; mt++)
#pragma unroll
            for (int nt = 0; nt < 4; nt++) {
                const int g = nt >> 1, hh = (nt & 1) * 2;
                mma16816(acc[mt][nt], aH[mt], bH[g][hh], bH[g][hh + 1]);
                mma16816(acc[mt][nt], aH[mt], bL[g][hh], bL[g][hh + 1]);
                mma16816(acc[mt][nt], aL[mt], bH[g][hh], bH[g][hh + 1]);
            }
    }

    // epilogue: split Wh into hi/lo fp16, write row-major [j][f]
#pragma unroll
    for (int mt = 0; mt < 4; mt++) {
        const int r0 = row0 + warpM * 64 + mt * 16 + (lane >> 2);
        const int r1 = r0 + 8;
#pragma unroll
        for (int nt = 0; nt < 4; nt++) {
            const int c0 = warpN * 32 + nt * 8 + (lane & 3) * 2;
            float a0 = acc[mt][nt][0], a1 = acc[mt][nt][1];
            float a2 = acc[mt][nt][2], a3 = acc[mt][nt][3];
            __half h0 = __float2half_rn(a0), h1 = __float2half_rn(a1);
            __half h2 = __float2half_rn(a2), h3 = __float2half_rn(a3);
            __half2 p0 = __halves2half2(h0, h1), p1 = __halves2half2(h2, h3);
            *(uint32_t*)(g_BH + (size_t)r0 * 128 + c0) = *(uint32_t*)&p0;
            *(uint32_t*)(g_BH + (size_t)r1 * 128 + c0) = *(uint32_t*)&p1;
            *(uint32_t*)(g_BL + (size_t)r0 * 128 + c0) =
                pack_f16x2(a0 - __half2float(h0), a1 - __half2float(h1));
            *(uint32_t*)(g_BL + (size_t)r1 * 128 + c0) =
                pack_f16x2(a2 - __half2float(h2), a3 - __half2float(h3));
        }
    }
}

// ---------------------------------------------------------------------------
// K2: per-node factors u=e^s, p=e^.2s, v=e^t, q=e^.2t (reads hi/lo Wh)
// ---------------------------------------------------------------------------
__global__ __launch_bounds__(256) void gat_st_kernel(const float* __restrict__ a)
{
    const int row = blockIdx.x * 8 + (threadIdx.x >> 5);
    const int lane = threadIdx.x & 31;
    const __half2* H = (const __half2*)(g_BH + (size_t)row * 128);
    const __half2* L = (const __half2*)(g_BL + (size_t)row * 128);
    float2 h0 = __half22float2(H[2 * lane]),     h1 = __half22float2(H[2 * lane + 1]);
    float2 l0 = __half22float2(L[2 * lane]),     l1 = __half22float2(L[2 * lane + 1]);
    float4 wv = make_float4(h0.x + l0.x, h0.y + l0.y, h1.x + l1.x, h1.y + l1.y);
    float4 as = ((const float4*)a)[lane];
    float4 ad = ((const float4*)a)[lane + 32];
    float sv = wv.x * as.x + wv.y * as.y + wv.z * as.z + wv.w * as.w;
    float tv = wv.x * ad.x + wv.y * ad.y + wv.z * ad.z + wv.w * ad.w;
#pragma unroll
    for (int o = 16; o > 0; o >>= 1) {
        sv += __shfl_down_sync(0xFFFFFFFFu, sv, o);
        tv += __shfl_down_sync(0xFFFFFFFFu, tv, o);
    }
    if (lane == 0) {
        g_u[row] = __expf(sv);   g_p[row] = __expf(0.2f * sv);
        g_v[row] = __expf(tv);   g_q[row] = __expf(0.2f * tv);
    }
}

// ---------------------------------------------------------------------------
// K4: fused P-construction + mma.sync GEMM + normalize epilogue.
//     P hi-only (rn); 2 products: P*WhH + P*WhL. Construct hidden under mma.
// ---------------------------------------------------------------------------
#define TK 64
#define SM_P(b)   ((b) * 16384)              // P   (128 x 64 fp16, 128B rows)
#define SM_BHO(b) (32768 + (b) * 16384)      // WhH (64 x 128 fp16, 256B rows)
#define SM_BLO(b) (65536 + (b) * 16384)      // WhL
#define SM_ADJ(b) (98304 + (b) * 32768)      // adj (128 x 64 int)
#define SM_ZR     163840
#define SM_ZI     164352
#define SMEM_SZ   164864

__global__ void __launch_bounds__(256, 1) gat_fused(
    const int* __restrict__ adj, float* __restrict__ out)
{
    extern __shared__ char sm[];
    const uint32_t sb = smem_u32(sm);
    const int tid = threadIdx.x, lane = tid & 31, wid = tid >> 5;
    const int b = blockIdx.y, i0 = blockIdx.x * 128;
    const int tx = tid & 15, ty = tid >> 4;

    const int* adjB = adj + ((size_t)(b * NNODE + i0)) * NNODE;
    const __half* BHg = g_BH + (size_t)b * NNODE * DIM;
    const __half* BLg = g_BL + (size_t)b * NNODE * DIM;

    float u_r[8], p_r[8];
#pragma unroll
    for (int m = 0; m < 8; m++) {
        int i = b * NNODE + i0 + ty + 16 * m;
        u_r[m] = g_u[i];  p_r[m] = g_p[i];
    }

    // prologue: adj(0), B(0), adj(1)
#pragma unroll
    for (int c2 = 0; c2 < 8; c2++) {
        int c = tid + 256 * c2;
        int row = c >> 4, col = c & 15;
        cp_async16(sb + SM_ADJ(0) + (uint32_t)(row * 256 + col * 16),
                   adjB + (size_t)row * NNODE + col * 4);
        cp_async16(sb + SM_ADJ(1) + (uint32_t)(row * 256 + col * 16),
                   adjB + (size_t)row * NNODE + TK + col * 4);
    }
#pragma unroll
    for (int c2 = 0; c2 < 4; c2++) {
        int c = tid + 256 * c2;
        int row = c >> 4, col = c & 15;
        uint32_t sw = SWB((uint32_t)(row * 256 + col * 16));
        cp_async16(sb + SM_BHO(0) + sw, BHg + (size_t)row * DIM + col * 8);
        cp_async16(sb + SM_BLO(0) + sw, BLg + (size_t)row * DIM + col * 8);
    }
    asm volatile("cp.async.commit_group;" ::: "memory");
    asm volatile("cp.async.wait_group 0;" ::: "memory");
    __syncthreads();

    float acc[4][4][4];
#pragma unroll
    for (int mt = 0; mt < 4; mt++)
#pragma unroll
        for (int nt = 0; nt < 4; nt++)
#pragma unroll
            for (int e = 0; e < 4; e++) acc[mt][nt][e] = 0.f;
    float zacc[8] = {0.f, 0.f, 0.f, 0.f, 0.f, 0.f, 0.f, 0.f};

    // construct P(0) into P[0] from ADJ(0)
    {
        float4 v4 = *(const float4*)(g_v + b * NNODE + 4 * tx);
        float4 q4 = *(const float4*)(g_q + b * NNODE + 4 * tx);
        char* P = sm + SM_P(0);
#pragma unroll
        for (int m = 0; m < 8; m++) {
            const int row = ty + 16 * m;
            int4 a4 = *(const int4*)(sm + SM_ADJ(0) + row * 256 + tx * 16);
            const float u = u_r[m], p = p_r[m];
            uint32_t w0 = __float_as_uint(fmaxf(u * v4.x, p * q4.x)) & (uint32_t)(-a4.x);
            uint32_t w1 = __float_as_uint(fmaxf(u * v4.y, p * q4.y)) & (uint32_t)(-a4.y);
            uint32_t w2 = __float_as_uint(fmaxf(u * v4.z, p * q4.z)) & (uint32_t)(-a4.z);
            uint32_t w3 = __float_as_uint(fmaxf(u * v4.w, p * q4.w)) & (uint32_t)(-a4.w);
            float f0 = __uint_as_float(w0), f1 = __uint_as_float(w1);
            float f2 = __uint_as_float(w2), f3 = __uint_as_float(w3);
            zacc[m] += (f0 + f1) + (f2 + f3);
            *(uint2*)(P + SWA((uint32_t)(row * 128 + tx * 8))) =
                make_uint2(pack_f16x2(f0, f1), pack_f16x2(f2, f3));
        }
    }

    const int warpM = wid >> 2, warpN = wid & 3;
    const int l15 = lane & 15, l16 = lane >> 4;
    const uint32_t xorv = (uint32_t)((l15 & 7) << 4);
    uint32_t aRow[4];
#pragma unroll
    for (int mt = 0; mt < 4; mt++)
        aRow[mt] = (uint32_t)((warpM * 64 + mt * 16 + l15) * 128);
    uint32_t bCol[2];
#pragma unroll
    for (int ng = 0; ng < 2; ng++)
        bCol[ng] = ((uint32_t)((warpN * 32 + ng * 16 + l16 * 8) * 2)) ^ xorv;
    const uint32_t bRow0 = (uint32_t)(l15 * 256);

    for (int kt = 0; kt < NNODE / TK; ++kt) {
        __syncthreads();   // P(kt), B(kt), adj(kt+1) visible; prior reads done
        const int cb = kt & 1, pb = (kt + 1) & 1;

        // stream B(kt+1), adj(kt+2)
        if (kt < 31) {
            const int j1 = (kt + 1) * TK;
#pragma unroll
            for (int c2 = 0; c2 < 4; c2++) {
                int c = tid + 256 * c2;
                int row = c >> 4, col = c & 15;
                uint32_t sw = SWB((uint32_t)(row * 256 + col * 16));
                cp_async16(sb + SM_BHO(pb) + sw, BHg + (size_t)(j1 + row) * DIM + col * 8);
                cp_async16(sb + SM_BLO(pb) + sw, BLg + (size_t)(j1 + row) * DIM + col * 8);
            }
        }
        if (kt < 30) {
            const int j2 = (kt + 2) * TK;
#pragma unroll
            for (int c2 = 0; c2 < 8; c2++) {
                int c = tid + 256 * c2;
                int row = c >> 4, col = c & 15;
                cp_async16(sb + SM_ADJ(cb) + (uint32_t)(row * 256 + col * 16),
                           adjB + (size_t)row * NNODE + j2 + col * 4);
            }
        }
        asm volatile("cp.async.commit_group;" ::: "memory");

        float4 vN, qN;
        if (kt < 31) {
            vN = *(const float4*)(g_v + b * NNODE + (kt + 1) * TK + 4 * tx);
            qN = *(const float4*)(g_q + b * NNODE + (kt + 1) * TK + 4 * tx);
        }

        const uint32_t Pb = sb + SM_P(cb), BHb = sb + SM_BHO(cb), BLb = sb + SM_BLO(cb);
#pragma unroll
        for (int kk = 0; kk < 4; ++kk) {
            const uint32_t aCol = ((uint32_t)(kk * 32 + l16 * 16)) ^ xorv;
            uint32_t aH[4][4];
#pragma unroll
            for (int mt = 0; mt < 4; mt++)
                ldsm_x4(aH[mt][0], aH[mt][1], aH[mt][2], aH[mt][3], Pb + aRow[mt] + aCol);
            const uint32_t bRow = bRow0 + (uint32_t)(kk * 4096);
            uint32_t bH[2][4], bL[2][4];
#pragma unroll
            for (int ng = 0; ng < 2; ng++) {
                ldsm_x4t(bH[ng][0], bH[ng][1], bH[ng][2], bH[ng][3], BHb + bRow + bCol[ng]);
                ldsm_x4t(bL[ng][0], bL[ng][1], bL[ng][2], bL[ng][3], BLb + bRow + bCol[ng]);
            }
#pragma unroll
            for (int mt = 0; mt < 4; mt++)
#pragma unroll
                for (int nt = 0; nt < 4; nt++) {
                    const int g = nt >> 1, hh = (nt & 1) * 2;
                    mma16816(acc[mt][nt], aH[mt], bH[g][hh], bH[g][hh + 1]);
                    mma16816(acc[mt][nt], aH[mt], bL[g][hh], bL[g][hh + 1]);
                }

            if (kk == 0 && kt < 31) {   // construct P(kt+1) while tensor drains
                char* P = sm + SM_P(pb);
#pragma unroll
                for (int m = 0; m < 8; m++) {
                    const int row = ty + 16 * m;
                    int4 a4 = *(const int4*)(sm + SM_ADJ(pb) + row * 256 + tx * 16);
                    const float u = u_r[m], p = p_r[m];
                    uint32_t w0 = __float_as_uint(fmaxf(u * vN.x, p * qN.x)) & (uint32_t)(-a4.x);
                    uint32_t w1 = __float_as_uint(fmaxf(u * vN.y, p * qN.y)) & (uint32_t)(-a4.y);
                    uint32_t w2 = __float_as_uint(fmaxf(u * vN.z, p * qN.z)) & (uint32_t)(-a4.z);
                    uint32_t w3 = __float_as_uint(fmaxf(u * vN.w, p * qN.w)) & (uint32_t)(-a4.w);
                    float f0 = __uint_as_float(w0), f1 = __uint_as_float(w1);
                    float f2 = __uint_as_float(w2), f3 = __uint_as_float(w3);
                    zacc[m] += (f0 + f1) + (f2 + f3);
                    *(uint2*)(P + SWA((uint32_t)(row * 128 + tx * 8))) =
                        make_uint2(pack_f16x2(f0, f1), pack_f16x2(f2, f3));
                }
            }
        }
        asm volatile("cp.async.wait_group 0;" ::: "memory");
    }

    // Z reduction and normalize
    float* zr = (float*)(sm + SM_ZR);
    float* zi = (float*)(sm + SM_ZI);
#pragma unroll
    for (int m = 0; m < 8; m++) {
        float z = zacc[m];
#pragma unroll
        for (int o = 1; o < 16; o <<= 1)
            z += __shfl_xor_sync(0xFFFFFFFFu, z, o);
        if (tx == 0) zr[ty + 16 * m] = z;
    }
    __syncthreads();
    if (tid < 128) {
        float z = zr[tid];
        zi[tid] = (z > 0.f) ? (1.f / z) : 0.f;
    }
    __syncthreads();

    float* outB = out + ((size_t)(b * NNODE + i0)) * DIM;
#pragma unroll
    for (int mt = 0; mt < 4; mt++) {
        const int r0 = warpM * 64 + mt * 16 + (lane >> 2);
        const int r1 = r0 + 8;
        const float z0 = zi[r0], z1 = zi[r1];
#pragma unroll
        for (int nt = 0; nt < 4; nt++) {
            const int c0 = warpN * 32 + nt * 8 + (lane & 3) * 2;
            *(float2*)(outB + (size_t)r0 * DIM + c0) =
                make_float2(acc[mt][nt][0] * z0, acc[mt][nt][1] * z0);
            *(float2*)(outB + (size_t)r1 * DIM + c0) =
                make_float2(acc[mt][nt][2] * z1, acc[mt][nt][3] * z1);
        }
    }
}

// ---------------------------------------------------------------------------
extern "C" void kernel_launch(void* const* d_in, const int* in_sizes, int n_in,
                              void* d_out, int out_size)
{
    const float* h   = (const float*)d_in[0];
    const int*   adj = (const int*)  d_in[1];
    const float* W   = (const float*)d_in[2];
    const float* a   = (const float*)d_in[3];
    float*       out = (float*)d_out;

    static int attr_set = 0;
    if (!attr_set) {
        cudaFuncSetAttribute(gat_wh_mma, cudaFuncAttributeMaxDynamicSharedMemorySize, K1_SMEM);
        cudaFuncSetAttribute(gat_fused, cudaFuncAttributeMaxDynamicSharedMemorySize, SMEM_SZ);
        attr_set = 1;
    }

    gat_wprep<<<64, 256>>>(W);
    gat_wh_mma<<<NROWS / 128, 256, K1_SMEM>>>(h);
    gat_st_kernel<<<NROWS / 8, 256>>>(a);
    gat_fused<<<dim3(NNODE / 128, BATCH), 256, SMEM_SZ>>>(adj, out);
}

// round 6
// speedup vs baseline: 6.7143x; 1.1690x over previous
#include <cuda_runtime.h>
#include <cuda_fp16.h>
#include <cstdint>

#define BATCH 8
#define NNODE 2048
#define DIM   128
#define NROWS (BATCH * NNODE)

__device__ float  g_u[NROWS], g_v[NROWS], g_p[NROWS], g_q[NROWS];
__device__ __half g_BH[NROWS * DIM];     // Wh hi fp16 [b][j][f]
__device__ __half g_BL[NROWS * DIM];     // Wh lo fp16
__device__ __half g_WTH[DIM * DIM];      // W^T hi fp16 [f][o]
__device__ __half g_WTL[DIM * DIM];      // W^T lo fp16

// ---------------- helpers ----------------
__device__ __forceinline__ uint32_t smem_u32(const void* p) {
    uint32_t a;
    asm("{ .reg .u64 t; cvta.to.shared.u64 t, %1; cvt.u32.u64 %0, t; }" : "=r"(a) : "l"(p));
    return a;
}
__device__ __forceinline__ void ldsm_x4(uint32_t& r0, uint32_t& r1, uint32_t& r2, uint32_t& r3, uint32_t a) {
    asm volatile("ldmatrix.sync.aligned.m8n8.x4.shared.b16 {%0,%1,%2,%3}, [%4];"
                 : "=r"(r0), "=r"(r1), "=r"(r2), "=r"(r3) : "r"(a));
}
__device__ __forceinline__ void ldsm_x4t(uint32_t& r0, uint32_t& r1, uint32_t& r2, uint32_t& r3, uint32_t a) {
    asm volatile("ldmatrix.sync.aligned.m8n8.x4.trans.shared.b16 {%0,%1,%2,%3}, [%4];"
                 : "=r"(r0), "=r"(r1), "=r"(r2), "=r"(r3) : "r"(a));
}
__device__ __forceinline__ void mma16816(float* c, const uint32_t* a, uint32_t b0, uint32_t b1) {
    asm volatile(
        "mma.sync.aligned.m16n8k16.row.col.f32.f16.f16.f32 "
        "{%0,%1,%2,%3}, {%4,%5,%6,%7}, {%8,%9}, {%0,%1,%2,%3};"
        : "+f"(c[0]), "+f"(c[1]), "+f"(c[2]), "+f"(c[3])
        : "r"(a[0]), "r"(a[1]), "r"(a[2]), "r"(a[3]), "r"(b0), "r"(b1));
}
__device__ __forceinline__ void cp_async16(uint32_t dst, const void* src) {
    asm volatile("cp.async.cg.shared.global [%0], [%1], 16;" :: "r"(dst), "l"(src));
}
__device__ __forceinline__ uint32_t pack_f16x2(float lo, float hi) {   // lower<-lo, upper<-hi
    uint32_t r;
    asm("cvt.rn.f16x2.f32 %0, %1, %2;" : "=r"(r) : "f"(hi), "f"(lo));
    return r;
}
#define SWA(o) ((o) ^ (((o) >> 3) & 0x70))   // 128B rows
#define SWB(o) ((o) ^ (((o) >> 4) & 0x70))   // 256B rows

// ---------------------------------------------------------------------------
// K0: W -> W^T hi/lo fp16
// ---------------------------------------------------------------------------
__global__ __launch_bounds__(256) void gat_wprep(const float* __restrict__ W)
{
    const int idx = blockIdx.x * 256 + threadIdx.x;
    const int o = idx >> 7, f = idx & 127;
    float w = W[idx];
    __half hi = __float2half_rn(w);
    float lo = w - __half2float(hi);
    g_WTH[f * 128 + o] = hi;
    g_WTL[f * 128 + o] = __float2half_rn(lo);
}

// ---------------------------------------------------------------------------
// K1: Wh = h @ W^T via mma.sync, hi/lo fp16, writes g_BH/g_BL directly.
// ---------------------------------------------------------------------------
#define K1_AH 0
#define K1_AL 32768
#define K1_BH 65536
#define K1_BL 98304
#define K1_SMEM 131072

__global__ void __launch_bounds__(256, 1) gat_wh_mma(const float* __restrict__ h)
{
    extern __shared__ char sm[];
    const uint32_t sb = smem_u32(sm);
    const int tid = threadIdx.x, lane = tid & 31, wid = tid >> 5;
    const int row0 = blockIdx.x * 128;

#pragma unroll
    for (int c = 0; c < 8; c++) {
        int idx = tid + 256 * c;
        int r = idx >> 4, col = idx & 15;
        uint32_t sw = (uint32_t)(r * 256 + ((col * 16) ^ ((r & 7) << 4)));
        cp_async16(sb + K1_BH + sw, g_WTH + r * 128 + col * 8);
        cp_async16(sb + K1_BL + sw, g_WTL + r * 128 + col * 8);
    }
    asm volatile("cp.async.commit_group;" ::: "memory");

#pragma unroll
    for (int c = 0; c < 16; c++) {
        int idx = tid + 256 * c;
        int r = idx >> 5, fq = idx & 31;
        float4 w = *(const float4*)(h + (size_t)(row0 + r) * 128 + fq * 4);
        __half h0 = __float2half_rn(w.x), h1 = __float2half_rn(w.y);
        __half h2 = __float2half_rn(w.z), h3 = __float2half_rn(w.w);
        float l0 = w.x - __half2float(h0), l1 = w.y - __half2float(h1);
        float l2 = w.z - __half2float(h2), l3 = w.w - __half2float(h3);
        uint32_t sw = (uint32_t)(r * 256 + ((fq * 8) ^ ((r & 7) << 4)));
        __half2 hA = __halves2half2(h0, h1), hB = __halves2half2(h2, h3);
        *(uint2*)(sm + K1_AH + sw) = make_uint2(*(uint32_t*)&hA, *(uint32_t*)&hB);
        *(uint2*)(sm + K1_AL + sw) = make_uint2(pack_f16x2(l0, l1), pack_f16x2(l2, l3));
    }
    asm volatile("cp.async.wait_group 0;" ::: "memory");
    __syncthreads();

    const int warpM = wid >> 2, warpN = wid & 3;
    const int l15 = lane & 15, l16 = lane >> 4;
    const uint32_t xorv = (uint32_t)((l15 & 7) << 4);

    float acc[4][4][4];
#pragma unroll
    for (int mt = 0; mt < 4; mt++)
#pragma unroll
        for (int nt = 0; nt < 4; nt++)
#pragma unroll
            for (int e = 0; e < 4; e++) acc[mt][nt][e] = 0.f;

    uint32_t aRow[4];
#pragma unroll
    for (int mt = 0; mt < 4; mt++)
        aRow[mt] = (uint32_t)((warpM * 64 + mt * 16 + l15) * 256);
    uint32_t bCol[2];
#pragma unroll
    for (int ng = 0; ng < 2; ng++)
        bCol[ng] = ((uint32_t)((warpN * 32 + ng * 16 + l16 * 8) * 2)) ^ xorv;

#pragma unroll
    for (int kk = 0; kk < 8; kk++) {
        const uint32_t aCol = ((uint32_t)(kk * 32 + l16 * 16)) ^ xorv;
        uint32_t aH[4][4], aL[4][4];
#pragma unroll
        for (int mt = 0; mt < 4; mt++) {
            ldsm_x4(aH[mt][0], aH[mt][1], aH[mt][2], aH[mt][3], sb + K1_AH + aRow[mt] + aCol);
            ldsm_x4(aL[mt][0], aL[mt][1], aL[mt][2], aL[mt][3], sb + K1_AL + aRow[mt] + aCol);
        }
        const uint32_t bRow = (uint32_t)((kk * 16 + l15) * 256);
        uint32_t bH[2][4], bL[2][4];
#pragma unroll
        for (int ng = 0; ng < 2; ng++) {
            ldsm_x4t(bH[ng][0], bH[ng][1], bH[ng][2], bH[ng][3], sb + K1_BH + bRow + bCol[ng]);
            ldsm_x4t(bL[ng][0], bL[ng][1], bL[ng][2], bL[ng][3], sb + K1_BL + bRow + bCol[ng]);
        }
#pragma unroll
        for (int mt = 0; mt < 4; mt++)
#pragma unroll
            for (int nt = 0; nt < 4; nt++) {
                const int g = nt >> 1, hh = (nt & 1) * 2;
                mma16816(acc[mt][nt], aH[mt], bH[g][hh], bH[g][hh + 1]);
                mma16816(acc[mt][nt], aH[mt], bL[g][hh], bL[g][hh + 1]);
                mma16816(acc[mt][nt], aL[mt], bH[g][hh], bH[g][hh + 1]);
            }
    }

#pragma unroll
    for (int mt = 0; mt < 4; mt++) {
        const int r0 = row0 + warpM * 64 + mt * 16 + (lane >> 2);
        const int r1 = r0 + 8;
#pragma unroll
        for (int nt = 0; nt < 4; nt++) {
            const int c0 = warpN * 32 + nt * 8 + (lane & 3) * 2;
            float a0 = acc[mt][nt][0], a1 = acc[mt][nt][1];
            float a2 = acc[mt][nt][2], a3 = acc[mt][nt][3];
            __half h0 = __float2half_rn(a0), h1 = __float2half_rn(a1);
            __half h2 = __float2half_rn(a2), h3 = __float2half_rn(a3);
            __half2 p0 = __halves2half2(h0, h1), p1 = __halves2half2(h2, h3);
            *(uint32_t*)(g_BH + (size_t)r0 * 128 + c0) = *(uint32_t*)&p0;
            *(uint32_t*)(g_BH + (size_t)r1 * 128 + c0) = *(uint32_t*)&p1;
            *(uint32_t*)(g_BL + (size_t)r0 * 128 + c0) =
                pack_f16x2(a0 - __half2float(h0), a1 - __half2float(h1));
            *(uint32_t*)(g_BL + (size_t)r1 * 128 + c0) =
                pack_f16x2(a2 - __half2float(h2), a3 - __half2float(h3));
        }
    }
}

// ---------------------------------------------------------------------------
// K2: per-node factors u=e^s, p=e^.2s, v=e^t, q=e^.2t
// ---------------------------------------------------------------------------
__global__ __launch_bounds__(256) void gat_st_kernel(const float* __restrict__ a)
{
    const int row = blockIdx.x * 8 + (threadIdx.x >> 5);
    const int lane = threadIdx.x & 31;
    const __half2* H = (const __half2*)(g_BH + (size_t)row * 128);
    const __half2* L = (const __half2*)(g_BL + (size_t)row * 128);
    float2 h0 = __half22float2(H[2 * lane]), h1 = __half22float2(H[2 * lane + 1]);
    float2 l0 = __half22float2(L[2 * lane]), l1 = __half22float2(L[2 * lane + 1]);
    float4 wv = make_float4(h0.x + l0.x, h0.y + l0.y, h1.x + l1.x, h1.y + l1.y);
    float4 as = ((const float4*)a)[lane];
    float4 ad = ((const float4*)a)[lane + 32];
    float sv = wv.x * as.x + wv.y * as.y + wv.z * as.z + wv.w * as.w;
    float tv = wv.x * ad.x + wv.y * ad.y + wv.z * ad.z + wv.w * ad.w;
#pragma unroll
    for (int o = 16; o > 0; o >>= 1) {
        sv += __shfl_down_sync(0xFFFFFFFFu, sv, o);
        tv += __shfl_down_sync(0xFFFFFFFFu, tv, o);
    }
    if (lane == 0) {
        g_u[row] = __expf(sv);   g_p[row] = __expf(0.2f * sv);
        g_v[row] = __expf(tv);   g_q[row] = __expf(0.2f * tv);
    }
}

// ---------------------------------------------------------------------------
// K4: fused. 512 threads, warp grid 4x4 (warp tile 32x32), adj gmem->regs,
//     B double-buffered cp.async, P construct overlapped after mma kk=0.
// ---------------------------------------------------------------------------
#define TK 64
#define SM_P(b)   ((b) * 16384)              // P (128 x 64 fp16, 128B rows)
#define SM_BHO(b) (32768 + (b) * 16384)      // WhH (64 x 128 fp16, 256B rows)
#define SM_BLO(b) (65536 + (b) * 16384)      // WhL
#define SM_ZR     98304
#define SM_ZI     98816
#define SMEM_SZ   99328

__global__ void __launch_bounds__(512, 1) gat_fused(
    const int* __restrict__ adj, float* __restrict__ out)
{
    extern __shared__ char sm[];
    const uint32_t sb = smem_u32(sm);
    const int tid = threadIdx.x, lane = tid & 31, wid = tid >> 5;
    const int b = blockIdx.y, i0 = blockIdx.x * 128;
    const int tx = tid & 15, ty = tid >> 4;     // ty: 0..31

    const int* adjB = adj + ((size_t)(b * NNODE + i0)) * NNODE;
    const __half* BHg = g_BH + (size_t)b * NNODE * DIM;
    const __half* BLg = g_BL + (size_t)b * NNODE * DIM;

    float u_r[4], p_r[4];
    const int* adjRow[4];
#pragma unroll
    for (int m = 0; m < 4; m++) {
        int il = ty + 32 * m;
        u_r[m] = g_u[b * NNODE + i0 + il];
        p_r[m] = g_p[b * NNODE + i0 + il];
        adjRow[m] = adjB + (size_t)il * NNODE + 4 * tx;
    }

    // prologue: B(0) cp.async; adj(0) -> regs; construct P(0); adj(1) -> regs
#pragma unroll
    for (int c2 = 0; c2 < 2; c2++) {
        int c = tid + 512 * c2;
        int row = c >> 4, col = c & 15;
        uint32_t sw = SWB((uint32_t)(row * 256 + col * 16));
        cp_async16(sb + SM_BHO(0) + sw, BHg + (size_t)row * DIM + col * 8);
        cp_async16(sb + SM_BLO(0) + sw, BLg + (size_t)row * DIM + col * 8);
    }
    asm volatile("cp.async.commit_group;" ::: "memory");

    float zacc[4] = {0.f, 0.f, 0.f, 0.f};

    {
        float4 v4 = *(const float4*)(g_v + b * NNODE + 4 * tx);
        float4 q4 = *(const float4*)(g_q + b * NNODE + 4 * tx);
        char* P = sm + SM_P(0);
#pragma unroll
        for (int m = 0; m < 4; m++) {
            const int row = ty + 32 * m;
            int4 a4 = *(const int4*)adjRow[m];
            const float u = u_r[m], p = p_r[m];
            uint32_t w0 = __float_as_uint(fmaxf(u * v4.x, p * q4.x)) & (uint32_t)(-a4.x);
            uint32_t w1 = __float_as_uint(fmaxf(u * v4.y, p * q4.y)) & (uint32_t)(-a4.y);
            uint32_t w2 = __float_as_uint(fmaxf(u * v4.z, p * q4.z)) & (uint32_t)(-a4.z);
            uint32_t w3 = __float_as_uint(fmaxf(u * v4.w, p * q4.w)) & (uint32_t)(-a4.w);
            float f0 = __uint_as_float(w0), f1 = __uint_as_float(w1);
            float f2 = __uint_as_float(w2), f3 = __uint_as_float(w3);
            zacc[m] += (f0 + f1) + (f2 + f3);
            *(uint2*)(P + SWA((uint32_t)(row * 128 + tx * 8))) =
                make_uint2(pack_f16x2(f0, f1), pack_f16x2(f2, f3));
        }
    }

    // adj(1) prefetch
    int4 aN[4];
#pragma unroll
    for (int m = 0; m < 4; m++) aN[m] = *(const int4*)(adjRow[m] + TK);

    float acc[2][4][4];
#pragma unroll
    for (int mt = 0; mt < 2; mt++)
#pragma unroll
        for (int nt = 0; nt < 4; nt++)
#pragma unroll
            for (int e = 0; e < 4; e++) acc[mt][nt][e] = 0.f;

    const int warpM = wid >> 2, warpN = wid & 3;
    const int l15 = lane & 15, l16 = lane >> 4;
    const uint32_t xorv = (uint32_t)((l15 & 7) << 4);
    uint32_t aRow[2];
#pragma unroll
    for (int mt = 0; mt < 2; mt++)
        aRow[mt] = (uint32_t)((warpM * 32 + mt * 16 + l15) * 128);
    uint32_t bCol[2];
#pragma unroll
    for (int ng = 0; ng < 2; ng++)
        bCol[ng] = ((uint32_t)((warpN * 32 + ng * 16 + l16 * 8) * 2)) ^ xorv;
    const uint32_t bRow0 = (uint32_t)(l15 * 256);

    asm volatile("cp.async.wait_group 0;" ::: "memory");
    __syncthreads();

    for (int kt = 0; kt < NNODE / TK; ++kt) {
        const int cb = kt & 1, pb = cb ^ 1;

        // stream B(kt+1)
        if (kt < 31) {
            const int j1 = (kt + 1) * TK;
#pragma unroll
            for (int c2 = 0; c2 < 2; c2++) {
                int c = tid + 512 * c2;
                int row = c >> 4, col = c & 15;
                uint32_t sw = SWB((uint32_t)(row * 256 + col * 16));
                cp_async16(sb + SM_BHO(pb) + sw, BHg + (size_t)(j1 + row) * DIM + col * 8);
                cp_async16(sb + SM_BLO(pb) + sw, BLg + (size_t)(j1 + row) * DIM + col * 8);
            }
        }
        asm volatile("cp.async.commit_group;" ::: "memory");

        float4 vN, qN;
        if (kt < 31) {
            vN = *(const float4*)(g_v + b * NNODE + (kt + 1) * TK + 4 * tx);
            qN = *(const float4*)(g_q + b * NNODE + (kt + 1) * TK + 4 * tx);
        }

        const uint32_t Pb = sb + SM_P(cb), BHb = sb + SM_BHO(cb), BLb = sb + SM_BLO(cb);
#pragma unroll
        for (int kk = 0; kk < 4; ++kk) {
            const uint32_t aCol = ((uint32_t)(kk * 32 + l16 * 16)) ^ xorv;
            uint32_t aH[2][4];
#pragma unroll
            for (int mt = 0; mt < 2; mt++)
                ldsm_x4(aH[mt][0], aH[mt][1], aH[mt][2], aH[mt][3], Pb + aRow[mt] + aCol);
            const uint32_t bRow = bRow0 + (uint32_t)(kk * 4096);
            uint32_t bH[2][4], bL[2][4];
#pragma unroll
            for (int ng = 0; ng < 2; ng++) {
                ldsm_x4t(bH[ng][0], bH[ng][1], bH[ng][2], bH[ng][3], BHb + bRow + bCol[ng]);
                ldsm_x4t(bL[ng][0], bL[ng][1], bL[ng][2], bL[ng][3], BLb + bRow + bCol[ng]);
            }
#pragma unroll
            for (int mt = 0; mt < 2; mt++)
#pragma unroll
                for (int nt = 0; nt < 4; nt++) {
                    const int g = nt >> 1, hh = (nt & 1) * 2;
                    mma16816(acc[mt][nt], aH[mt], bH[g][hh], bH[g][hh + 1]);
                    mma16816(acc[mt][nt], aH[mt], bL[g][hh], bL[g][hh + 1]);
                }

            if (kk == 0 && kt < 31) {
                // construct P(kt+1) from adj regs while tensor pipe drains
                char* P = sm + SM_P(pb);
#pragma unroll
                for (int m = 0; m < 4; m++) {
                    const int row = ty + 32 * m;
                    const float u = u_r[m], p = p_r[m];
                    uint32_t w0 = __float_as_uint(fmaxf(u * vN.x, p * qN.x)) & (uint32_t)(-aN[m].x);
                    uint32_t w1 = __float_as_uint(fmaxf(u * vN.y, p * qN.y)) & (uint32_t)(-aN[m].y);
                    uint32_t w2 = __float_as_uint(fmaxf(u * vN.z, p * qN.z)) & (uint32_t)(-aN[m].z);
                    uint32_t w3 = __float_as_uint(fmaxf(u * vN.w, p * qN.w)) & (uint32_t)(-aN[m].w);
                    float f0 = __uint_as_float(w0), f1 = __uint_as_float(w1);
                    float f2 = __uint_as_float(w2), f3 = __uint_as_float(w3);
                    zacc[m] += (f0 + f1) + (f2 + f3);
                    *(uint2*)(P + SWA((uint32_t)(row * 128 + tx * 8))) =
                        make_uint2(pack_f16x2(f0, f1), pack_f16x2(f2, f3));
                }
                // prefetch adj(kt+2) into regs
                if (kt < 30) {
                    const int j2 = (kt + 2) * TK;
#pragma unroll
                    for (int m = 0; m < 4; m++)
                        aN[m] = *(const int4*)(adjRow[m] + j2);
                }
            }
        }
        asm volatile("cp.async.wait_group 0;" ::: "memory");
        __syncthreads();
    }

    // Z reduction and normalize
    float* zr = (float*)(sm + SM_ZR);
    float* zi = (float*)(sm + SM_ZI);
#pragma unroll
    for (int m = 0; m < 4; m++) {
        float z = zacc[m];
#pragma unroll
        for (int o = 1; o < 16; o <<= 1)
            z += __shfl_xor_sync(0xFFFFFFFFu, z, o);
        if (tx == 0) zr[ty + 32 * m] = z;
    }
    __syncthreads();
    if (tid < 128) {
        float z = zr[tid];
        zi[tid] = (z > 0.f) ? (1.f / z) : 0.f;
    }
    __syncthreads();

    float* outB = out + ((size_t)(b * NNODE + i0)) * DIM;
#pragma unroll
    for (int mt = 0; mt < 2; mt++) {
        const int r0 = warpM * 32 + mt * 16 + (lane >> 2);
        const int r1 = r0 + 8;
        const float z0 = zi[r0], z1 = zi[r1];
#pragma unroll
        for (int nt = 0; nt < 4; nt++) {
            const int c0 = warpN * 32 + nt * 8 + (lane & 3) * 2;
            *(float2*)(outB + (size_t)r0 * DIM + c0) =
                make_float2(acc[mt][nt][0] * z0, acc[mt][nt][1] * z0);
            *(float2*)(outB + (size_t)r1 * DIM + c0) =
                make_float2(acc[mt][nt][2] * z1, acc[mt][nt][3] * z1);
        }
    }
}

// ---------------------------------------------------------------------------
extern "C" void kernel_launch(void* const* d_in, const int* in_sizes, int n_in,
                              void* d_out, int out_size)
{
    const float* h   = (const float*)d_in[0];
    const int*   adj = (const int*)  d_in[1];
    const float* W   = (const float*)d_in[2];
    const float* a   = (const float*)d_in[3];
    float*       out = (float*)d_out;

    static int attr_set = 0;
    if (!attr_set) {
        cudaFuncSetAttribute(gat_wh_mma, cudaFuncAttributeMaxDynamicSharedMemorySize, K1_SMEM);
        cudaFuncSetAttribute(gat_fused, cudaFuncAttributeMaxDynamicSharedMemorySize, SMEM_SZ);
        attr_set = 1;
    }

    gat_wprep<<<64, 256>>>(W);
    gat_wh_mma<<<NROWS / 128, 256, K1_SMEM>>>(h);
    gat_st_kernel<<<NROWS / 8, 256>>>(a);
    gat_fused<<<dim3(NNODE / 128, BATCH), 512, SMEM_SZ>>>(adj, out);
}

// round 7
// speedup vs baseline: 8.7127x; 1.2976x over previous
#include <cuda_runtime.h>
#include <cuda_fp16.h>
#include <cstdint>

#define BATCH 8
#define NNODE 2048
#define DIM   128
#define NROWS (BATCH * NNODE)

__device__ float  g_u[NROWS], g_v[NROWS], g_p[NROWS], g_q[NROWS];
__device__ __half g_BH[NROWS * DIM];     // Wh hi fp16 [b][j][f]  (GEMM B + K2)
__device__ __half g_BL[NROWS * DIM];     // Wh lo fp16  (K2 only: exact s,t)
__device__ __half g_WTH[DIM * DIM];      // W^T hi fp16 [f][o]
__device__ __half g_WTL[DIM * DIM];      // W^T lo fp16

// ---------------- helpers ----------------
__device__ __forceinline__ uint32_t smem_u32(const void* p) {
    uint32_t a;
    asm("{ .reg .u64 t; cvta.to.shared.u64 t, %1; cvt.u32.u64 %0, t; }" : "=r"(a) : "l"(p));
    return a;
}
__device__ __forceinline__ void ldsm_x4(uint32_t& r0, uint32_t& r1, uint32_t& r2, uint32_t& r3, uint32_t a) {
    asm volatile("ldmatrix.sync.aligned.m8n8.x4.shared.b16 {%0,%1,%2,%3}, [%4];"
                 : "=r"(r0), "=r"(r1), "=r"(r2), "=r"(r3) : "r"(a));
}
__device__ __forceinline__ void ldsm_x4t(uint32_t& r0, uint32_t& r1, uint32_t& r2, uint32_t& r3, uint32_t a) {
    asm volatile("ldmatrix.sync.aligned.m8n8.x4.trans.shared.b16 {%0,%1,%2,%3}, [%4];"
                 : "=r"(r0), "=r"(r1), "=r"(r2), "=r"(r3) : "r"(a));
}
__device__ __forceinline__ void mma16816(float* c, const uint32_t* a, uint32_t b0, uint32_t b1) {
    asm volatile(
        "mma.sync.aligned.m16n8k16.row.col.f32.f16.f16.f32 "
        "{%0,%1,%2,%3}, {%4,%5,%6,%7}, {%8,%9}, {%0,%1,%2,%3};"
        : "+f"(c[0]), "+f"(c[1]), "+f"(c[2]), "+f"(c[3])
        : "r"(a[0]), "r"(a[1]), "r"(a[2]), "r"(a[3]), "r"(b0), "r"(b1));
}
__device__ __forceinline__ void cp_async16(uint32_t dst, const void* src) {
    asm volatile("cp.async.cg.shared.global [%0], [%1], 16;" :: "r"(dst), "l"(src));
}
__device__ __forceinline__ uint32_t pack_f16x2(float lo, float hi) {   // lower<-lo, upper<-hi
    uint32_t r;
    asm("cvt.rn.f16x2.f32 %0, %1, %2;" : "=r"(r) : "f"(hi), "f"(lo));
    return r;
}
#define SWA(o) ((o) ^ (((o) >> 3) & 0x70))   // 128B rows
#define SWB(o) ((o) ^ (((o) >> 4) & 0x70))   // 256B rows

// ---------------------------------------------------------------------------
// K0: W -> W^T hi/lo fp16
// ---------------------------------------------------------------------------
__global__ __launch_bounds__(256) void gat_wprep(const float* __restrict__ W)
{
    const int idx = blockIdx.x * 256 + threadIdx.x;
    const int o = idx >> 7, f = idx & 127;
    float w = W[idx];
    __half hi = __float2half_rn(w);
    float lo = w - __half2float(hi);
    g_WTH[f * 128 + o] = hi;
    g_WTL[f * 128 + o] = __float2half_rn(lo);
}

// ---------------------------------------------------------------------------
// K1: Wh = h @ W^T via mma.sync (3 hi/lo products -> ~fp32 Wh), writes BH/BL.
// ---------------------------------------------------------------------------
#define K1_AH 0
#define K1_AL 32768
#define K1_BH 65536
#define K1_BL 98304
#define K1_SMEM 131072

__global__ void __launch_bounds__(256, 1) gat_wh_mma(const float* __restrict__ h)
{
    extern __shared__ char sm[];
    const uint32_t sb = smem_u32(sm);
    const int tid = threadIdx.x, lane = tid & 31, wid = tid >> 5;
    const int row0 = blockIdx.x * 128;

#pragma unroll
    for (int c = 0; c < 8; c++) {
        int idx = tid + 256 * c;
        int r = idx >> 4, col = idx & 15;
        uint32_t sw = (uint32_t)(r * 256 + ((col * 16) ^ ((r & 7) << 4)));
        cp_async16(sb + K1_BH + sw, g_WTH + r * 128 + col * 8);
        cp_async16(sb + K1_BL + sw, g_WTL + r * 128 + col * 8);
    }
    asm volatile("cp.async.commit_group;" ::: "memory");

#pragma unroll
    for (int c = 0; c < 16; c++) {
        int idx = tid + 256 * c;
        int r = idx >> 5, fq = idx & 31;
        float4 w = *(const float4*)(h + (size_t)(row0 + r) * 128 + fq * 4);
        __half h0 = __float2half_rn(w.x), h1 = __float2half_rn(w.y);
        __half h2 = __float2half_rn(w.z), h3 = __float2half_rn(w.w);
        float l0 = w.x - __half2float(h0), l1 = w.y - __half2float(h1);
        float l2 = w.z - __half2float(h2), l3 = w.w - __half2float(h3);
        uint32_t sw = (uint32_t)(r * 256 + ((fq * 8) ^ ((r & 7) << 4)));
        __half2 hA = __halves2half2(h0, h1), hB = __halves2half2(h2, h3);
        *(uint2*)(sm + K1_AH + sw) = make_uint2(*(uint32_t*)&hA, *(uint32_t*)&hB);
        *(uint2*)(sm + K1_AL + sw) = make_uint2(pack_f16x2(l0, l1), pack_f16x2(l2, l3));
    }
    asm volatile("cp.async.wait_group 0;" ::: "memory");
    __syncthreads();

    const int warpM = wid >> 2, warpN = wid & 3;
    const int l15 = lane & 15, l16 = lane >> 4;
    const uint32_t xorv = (uint32_t)((l15 & 7) << 4);

    float acc[4][4][4];
#pragma unroll
    for (int mt = 0; mt < 4; mt++)
#pragma unroll
        for (int nt = 0; nt < 4; nt++)
#pragma unroll
            for (int e = 0; e < 4; e++) acc[mt][nt][e] = 0.f;

    uint32_t aRow[4];
#pragma unroll
    for (int mt = 0; mt < 4; mt++)
        aRow[mt] = (uint32_t)((warpM * 64 + mt * 16 + l15) * 256);
    uint32_t bCol[2];
#pragma unroll
    for (int ng = 0; ng < 2; ng++)
        bCol[ng] = ((uint32_t)((warpN * 32 + ng * 16 + l16 * 8) * 2)) ^ xorv;

#pragma unroll
    for (int kk = 0; kk < 8; kk++) {
        const uint32_t aCol = ((uint32_t)(kk * 32 + l16 * 16)) ^ xorv;
        uint32_t aH[4][4], aL[4][4];
#pragma unroll
        for (int mt = 0; mt < 4; mt++) {
            ldsm_x4(aH[mt][0], aH[mt][1], aH[mt][2], aH[mt][3], sb + K1_AH + aRow[mt] + aCol);
            ldsm_x4(aL[mt][0], aL[mt][1], aL[mt][2], aL[mt][3], sb + K1_AL + aRow[mt] + aCol);
        }
        const uint32_t bRow = (uint32_t)((kk * 16 + l15) * 256);
        uint32_t bH[2][4], bL[2][4];
#pragma unroll
        for (int ng = 0; ng < 2; ng++) {
            ldsm_x4t(bH[ng][0], bH[ng][1], bH[ng][2], bH[ng][3], sb + K1_BH + bRow + bCol[ng]);
            ldsm_x4t(bL[ng][0], bL[ng][1], bL[ng][2], bL[ng][3], sb + K1_BL + bRow + bCol[ng]);
        }
#pragma unroll
        for (int mt = 0; mt < 4; mt++)
#pragma unroll
            for (int nt = 0; nt < 4; nt++) {
                const int g = nt >> 1, hh = (nt & 1) * 2;
                mma16816(acc[mt][nt], aH[mt], bH[g][hh], bH[g][hh + 1]);
                mma16816(acc[mt][nt], aH[mt], bL[g][hh], bL[g][hh + 1]);
                mma16816(acc[mt][nt], aL[mt], bH[g][hh], bH[g][hh + 1]);
            }
    }

#pragma unroll
    for (int mt = 0; mt < 4; mt++) {
        const int r0 = row0 + warpM * 64 + mt * 16 + (lane >> 2);
        const int r1 = r0 + 8;
#pragma unroll
        for (int nt = 0; nt < 4; nt++) {
            const int c0 = warpN * 32 + nt * 8 + (lane & 3) * 2;
            float a0 = acc[mt][nt][0], a1 = acc[mt][nt][1];
            float a2 = acc[mt][nt][2], a3 = acc[mt][nt][3];
            __half h0 = __float2half_rn(a0), h1 = __float2half_rn(a1);
            __half h2 = __float2half_rn(a2), h3 = __float2half_rn(a3);
            __half2 p0 = __halves2half2(h0, h1), p1 = __halves2half2(h2, h3);
            *(uint32_t*)(g_BH + (size_t)r0 * 128 + c0) = *(uint32_t*)&p0;
            *(uint32_t*)(g_BH + (size_t)r1 * 128 + c0) = *(uint32_t*)&p1;
            *(uint32_t*)(g_BL + (size_t)r0 * 128 + c0) =
                pack_f16x2(a0 - __half2float(h0), a1 - __half2float(h1));
            *(uint32_t*)(g_BL + (size_t)r1 * 128 + c0) =
                pack_f16x2(a2 - __half2float(h2), a3 - __half2float(h3));
        }
    }
}

// ---------------------------------------------------------------------------
// K2: per-node factors (exact s,t from hi+lo Wh)
// ---------------------------------------------------------------------------
__global__ __launch_bounds__(256) void gat_st_kernel(const float* __restrict__ a)
{
    const int row = blockIdx.x * 8 + (threadIdx.x >> 5);
    const int lane = threadIdx.x & 31;
    const __half2* H = (const __half2*)(g_BH + (size_t)row * 128);
    const __half2* L = (const __half2*)(g_BL + (size_t)row * 128);
    float2 h0 = __half22float2(H[2 * lane]), h1 = __half22float2(H[2 * lane + 1]);
    float2 l0 = __half22float2(L[2 * lane]), l1 = __half22float2(L[2 * lane + 1]);
    float4 wv = make_float4(h0.x + l0.x, h0.y + l0.y, h1.x + l1.x, h1.y + l1.y);
    float4 as = ((const float4*)a)[lane];
    float4 ad = ((const float4*)a)[lane + 32];
    float sv = wv.x * as.x + wv.y * as.y + wv.z * as.z + wv.w * as.w;
    float tv = wv.x * ad.x + wv.y * ad.y + wv.z * ad.z + wv.w * ad.w;
#pragma unroll
    for (int o = 16; o > 0; o >>= 1) {
        sv += __shfl_down_sync(0xFFFFFFFFu, sv, o);
        tv += __shfl_down_sync(0xFFFFFFFFu, tv, o);
    }
    if (lane == 0) {
        g_u[row] = __expf(sv);   g_p[row] = __expf(0.2f * sv);
        g_v[row] = __expf(tv);   g_q[row] = __expf(0.2f * tv);
    }
}

// ---------------------------------------------------------------------------
// K4: fused. M-tile 64, 256 threads (8 warps, 4x... warp grid 2x4, tile 32x32),
//     SINGLE product P*WhH, adj gmem->regs, B double-buffered, 2 CTAs/SM.
// ---------------------------------------------------------------------------
#define TK 64
#define SM_P(b)   ((b) * 8192)               // P (64 x 64 fp16, 128B rows)
#define SM_BHO(b) (16384 + (b) * 16384)      // WhH (64 x 128 fp16, 256B rows)
#define SM_ZR     49152
#define SM_ZI     49408
#define SMEM_SZ   49664

__global__ void __launch_bounds__(256, 2) gat_fused(
    const int* __restrict__ adj, float* __restrict__ out)
{
    extern __shared__ char sm[];
    const uint32_t sb = smem_u32(sm);
    const int tid = threadIdx.x, lane = tid & 31, wid = tid >> 5;
    const int b = blockIdx.y, i0 = blockIdx.x * 64;
    const int tx = tid & 15, ty = tid >> 4;     // ty: 0..15

    const int* adjB = adj + ((size_t)(b * NNODE + i0)) * NNODE;
    const __half* BHg = g_BH + (size_t)b * NNODE * DIM;

    float u_r[4], p_r[4];
    const int* adjRow[4];
#pragma unroll
    for (int m = 0; m < 4; m++) {
        int il = ty + 16 * m;                    // rows 0..63
        u_r[m] = g_u[b * NNODE + i0 + il];
        p_r[m] = g_p[b * NNODE + i0 + il];
        adjRow[m] = adjB + (size_t)il * NNODE + 4 * tx;
    }

    // prologue: B(0) cp.async
#pragma unroll
    for (int c2 = 0; c2 < 4; c2++) {
        int c = tid + 256 * c2;
        int row = c >> 4, col = c & 15;
        uint32_t sw = SWB((uint32_t)(row * 256 + col * 16));
        cp_async16(sb + SM_BHO(0) + sw, BHg + (size_t)row * DIM + col * 8);
    }
    asm volatile("cp.async.commit_group;" ::: "memory");

    float zacc[4] = {0.f, 0.f, 0.f, 0.f};

    // construct P(0) directly from gmem adj
    {
        float4 v4 = *(const float4*)(g_v + b * NNODE + 4 * tx);
        float4 q4 = *(const float4*)(g_q + b * NNODE + 4 * tx);
        char* P = sm + SM_P(0);
#pragma unroll
        for (int m = 0; m < 4; m++) {
            const int row = ty + 16 * m;
            int4 a4 = *(const int4*)adjRow[m];
            const float u = u_r[m], p = p_r[m];
            uint32_t w0 = __float_as_uint(fmaxf(u * v4.x, p * q4.x)) & (uint32_t)(-a4.x);
            uint32_t w1 = __float_as_uint(fmaxf(u * v4.y, p * q4.y)) & (uint32_t)(-a4.y);
            uint32_t w2 = __float_as_uint(fmaxf(u * v4.z, p * q4.z)) & (uint32_t)(-a4.z);
            uint32_t w3 = __float_as_uint(fmaxf(u * v4.w, p * q4.w)) & (uint32_t)(-a4.w);
            float f0 = __uint_as_float(w0), f1 = __uint_as_float(w1);
            float f2 = __uint_as_float(w2), f3 = __uint_as_float(w3);
            zacc[m] += (f0 + f1) + (f2 + f3);
            *(uint2*)(P + SWA((uint32_t)(row * 128 + tx * 8))) =
                make_uint2(pack_f16x2(f0, f1), pack_f16x2(f2, f3));
        }
    }

    // adj(1) prefetch into regs
    int4 aN[4];
#pragma unroll
    for (int m = 0; m < 4; m++) aN[m] = *(const int4*)(adjRow[m] + TK);

    float acc[2][4][4];
#pragma unroll
    for (int mt = 0; mt < 2; mt++)
#pragma unroll
        for (int nt = 0; nt < 4; nt++)
#pragma unroll
            for (int e = 0; e < 4; e++) acc[mt][nt][e] = 0.f;

    const int warpM = wid >> 2, warpN = wid & 3;   // 2 x 4
    const int l15 = lane & 15, l16 = lane >> 4;
    const uint32_t xorv = (uint32_t)((l15 & 7) << 4);
    uint32_t aRow[2];
#pragma unroll
    for (int mt = 0; mt < 2; mt++)
        aRow[mt] = (uint32_t)((warpM * 32 + mt * 16 + l15) * 128);
    uint32_t bCol[2];
#pragma unroll
    for (int ng = 0; ng < 2; ng++)
        bCol[ng] = ((uint32_t)((warpN * 32 + ng * 16 + l16 * 8) * 2)) ^ xorv;
    const uint32_t bRow0 = (uint32_t)(l15 * 256);

    asm volatile("cp.async.wait_group 0;" ::: "memory");
    __syncthreads();

    for (int kt = 0; kt < NNODE / TK; ++kt) {
        const int cb = kt & 1, pb = cb ^ 1;

        // stream B(kt+1)
        if (kt < 31) {
            const int j1 = (kt + 1) * TK;
#pragma unroll
            for (int c2 = 0; c2 < 4; c2++) {
                int c = tid + 256 * c2;
                int row = c >> 4, col = c & 15;
                uint32_t sw = SWB((uint32_t)(row * 256 + col * 16));
                cp_async16(sb + SM_BHO(pb) + sw, BHg + (size_t)(j1 + row) * DIM + col * 8);
            }
        }
        asm volatile("cp.async.commit_group;" ::: "memory");

        float4 vN, qN;
        if (kt < 31) {
            vN = *(const float4*)(g_v + b * NNODE + (kt + 1) * TK + 4 * tx);
            qN = *(const float4*)(g_q + b * NNODE + (kt + 1) * TK + 4 * tx);
        }

        const uint32_t Pb = sb + SM_P(cb), BHb = sb + SM_BHO(cb);
#pragma unroll
        for (int kk = 0; kk < 4; ++kk) {
            const uint32_t aCol = ((uint32_t)(kk * 32 + l16 * 16)) ^ xorv;
            uint32_t aH[2][4];
#pragma unroll
            for (int mt = 0; mt < 2; mt++)
                ldsm_x4(aH[mt][0], aH[mt][1], aH[mt][2], aH[mt][3], Pb + aRow[mt] + aCol);
            const uint32_t bRow = bRow0 + (uint32_t)(kk * 4096);
            uint32_t bH[2][4];
#pragma unroll
            for (int ng = 0; ng < 2; ng++)
                ldsm_x4t(bH[ng][0], bH[ng][1], bH[ng][2], bH[ng][3], BHb + bRow + bCol[ng]);
#pragma unroll
            for (int mt = 0; mt < 2; mt++)
#pragma unroll
                for (int nt = 0; nt < 4; nt++) {
                    const int g = nt >> 1, hh = (nt & 1) * 2;
                    mma16816(acc[mt][nt], aH[mt], bH[g][hh], bH[g][hh + 1]);
                }

            if (kk == 0 && kt < 31) {
                // construct P(kt+1) while tensor pipe drains
                char* P = sm + SM_P(pb);
#pragma unroll
                for (int m = 0; m < 4; m++) {
                    const int row = ty + 16 * m;
                    const float u = u_r[m], p = p_r[m];
                    uint32_t w0 = __float_as_uint(fmaxf(u * vN.x, p * qN.x)) & (uint32_t)(-aN[m].x);
                    uint32_t w1 = __float_as_uint(fmaxf(u * vN.y, p * qN.y)) & (uint32_t)(-aN[m].y);
                    uint32_t w2 = __float_as_uint(fmaxf(u * vN.z, p * qN.z)) & (uint32_t)(-aN[m].z);
                    uint32_t w3 = __float_as_uint(fmaxf(u * vN.w, p * qN.w)) & (uint32_t)(-aN[m].w);
                    float f0 = __uint_as_float(w0), f1 = __uint_as_float(w1);
                    float f2 = __uint_as_float(w2), f3 = __uint_as_float(w3);
                    zacc[m] += (f0 + f1) + (f2 + f3);
                    *(uint2*)(P + SWA((uint32_t)(row * 128 + tx * 8))) =
                        make_uint2(pack_f16x2(f0, f1), pack_f16x2(f2, f3));
                }
                if (kt < 30) {
                    const int j2 = (kt + 2) * TK;
#pragma unroll
                    for (int m = 0; m < 4; m++)
                        aN[m] = *(const int4*)(adjRow[m] + j2);
                }
            }
        }
        asm volatile("cp.async.wait_group 0;" ::: "memory");
        __syncthreads();
    }

    // Z reduction and normalize
    float* zr = (float*)(sm + SM_ZR);
    float* zi = (float*)(sm + SM_ZI);
#pragma unroll
    for (int m = 0; m < 4; m++) {
        float z = zacc[m];
#pragma unroll
        for (int o = 1; o < 16; o <<= 1)
            z += __shfl_xor_sync(0xFFFFFFFFu, z, o);
        if (tx == 0) zr[ty + 16 * m] = z;
    }
    __syncthreads();
    if (tid < 64) {
        float z = zr[tid];
        zi[tid] = (z > 0.f) ? (1.f / z) : 0.f;
    }
    __syncthreads();

    float* outB = out + ((size_t)(b * NNODE + i0)) * DIM;
#pragma unroll
    for (int mt = 0; mt < 2; mt++) {
        const int r0 = warpM * 32 + mt * 16 + (lane >> 2);
        const int r1 = r0 + 8;
        const float z0 = zi[r0], z1 = zi[r1];
#pragma unroll
        for (int nt = 0; nt < 4; nt++) {
            const int c0 = warpN * 32 + nt * 8 + (lane & 3) * 2;
            *(float2*)(outB + (size_t)r0 * DIM + c0) =
                make_float2(acc[mt][nt][0] * z0, acc[mt][nt][1] * z0);
            *(float2*)(outB + (size_t)r1 * DIM + c0) =
                make_float2(acc[mt][nt][2] * z1, acc[mt][nt][3] * z1);
        }
    }
}

// ---------------------------------------------------------------------------
extern "C" void kernel_launch(void* const* d_in, const int* in_sizes, int n_in,
                              void* d_out, int out_size)
{
    const float* h   = (const float*)d_in[0];
    const int*   adj = (const int*)  d_in[1];
    const float* W   = (const float*)d_in[2];
    const float* a   = (const float*)d_in[3];
    float*       out = (float*)d_out;

    static int attr_set = 0;
    if (!attr_set) {
        cudaFuncSetAttribute(gat_wh_mma, cudaFuncAttributeMaxDynamicSharedMemorySize, K1_SMEM);
        cudaFuncSetAttribute(gat_fused, cudaFuncAttributeMaxDynamicSharedMemorySize, SMEM_SZ);
        attr_set = 1;
    }

    gat_wprep<<<64, 256>>>(W);
    gat_wh_mma<<<NROWS / 128, 256, K1_SMEM>>>(h);
    gat_st_kernel<<<NROWS / 8, 256>>>(a);
    gat_fused<<<dim3(NNODE / 64, BATCH), 256, SMEM_SZ>>>(adj, out);
}

// round 8
// speedup vs baseline: 8.7397x; 1.0031x over previous
#include <cuda_runtime.h>
#include <cuda_fp16.h>
#include <cstdint>

#define BATCH 8
#define NNODE 2048
#define DIM   128
#define NROWS (BATCH * NNODE)

__device__ float  g_u[NROWS], g_v[NROWS], g_p[NROWS], g_q[NROWS];
__device__ __half g_BH[NROWS * DIM];     // Wh fp16 rn [b][j][f]
__device__ __half g_WTH[DIM * DIM];      // W^T hi fp16 [f][o]
__device__ __half g_WTL[DIM * DIM];      // W^T lo fp16

// ---------------- helpers ----------------
__device__ __forceinline__ uint32_t smem_u32(const void* p) {
    uint32_t a;
    asm("{ .reg .u64 t; cvta.to.shared.u64 t, %1; cvt.u32.u64 %0, t; }" : "=r"(a) : "l"(p));
    return a;
}
__device__ __forceinline__ void ldsm_x4(uint32_t& r0, uint32_t& r1, uint32_t& r2, uint32_t& r3, uint32_t a) {
    asm volatile("ldmatrix.sync.aligned.m8n8.x4.shared.b16 {%0,%1,%2,%3}, [%4];"
                 : "=r"(r0), "=r"(r1), "=r"(r2), "=r"(r3) : "r"(a));
}
__device__ __forceinline__ void ldsm_x4t(uint32_t& r0, uint32_t& r1, uint32_t& r2, uint32_t& r3, uint32_t a) {
    asm volatile("ldmatrix.sync.aligned.m8n8.x4.trans.shared.b16 {%0,%1,%2,%3}, [%4];"
                 : "=r"(r0), "=r"(r1), "=r"(r2), "=r"(r3) : "r"(a));
}
__device__ __forceinline__ void mma16816(float* c, const uint32_t* a, uint32_t b0, uint32_t b1) {
    asm volatile(
        "mma.sync.aligned.m16n8k16.row.col.f32.f16.f16.f32 "
        "{%0,%1,%2,%3}, {%4,%5,%6,%7}, {%8,%9}, {%0,%1,%2,%3};"
        : "+f"(c[0]), "+f"(c[1]), "+f"(c[2]), "+f"(c[3])
        : "r"(a[0]), "r"(a[1]), "r"(a[2]), "r"(a[3]), "r"(b0), "r"(b1));
}
__device__ __forceinline__ void cp_async16(uint32_t dst, const void* src) {
    asm volatile("cp.async.cg.shared.global [%0], [%1], 16;" :: "r"(dst), "l"(src));
}
__device__ __forceinline__ uint32_t pack_f16x2(float lo, float hi) {   // lower<-lo, upper<-hi
    uint32_t r;
    asm("cvt.rn.f16x2.f32 %0, %1, %2;" : "=r"(r) : "f"(hi), "f"(lo));
    return r;
}

// ---------------------------------------------------------------------------
// K0: W -> W^T hi/lo fp16
// ---------------------------------------------------------------------------
__global__ __launch_bounds__(256) void gat_wprep(const float* __restrict__ W)
{
    const int idx = blockIdx.x * 256 + threadIdx.x;
    const int o = idx >> 7, f = idx & 127;
    float w = W[idx];
    __half hi = __float2half_rn(w);
    float lo = w - __half2float(hi);
    g_WTH[f * 128 + o] = hi;
    g_WTL[f * 128 + o] = __float2half_rn(lo);
}

// ---------------------------------------------------------------------------
// K1: Wh = h @ W^T (hi/lo mma, exact-ish fp32 acc) + s,t + exp factors.
//     256 CTAs x 64 rows (2/SM). Writes g_BH (fp16 rn) and g_u/p/v/q.
// ---------------------------------------------------------------------------
#define A_AH   0
#define A_AL   16384
#define A_BH   32768
#define A_BL   65536
#define A_SRED 98304        // sredS 64*4 f32 = 1024, sredT at +1024
#define A_SMEM 100352

__global__ void __launch_bounds__(256, 2) gat_wh_st(
    const float* __restrict__ h, const float* __restrict__ a)
{
    extern __shared__ char sm[];
    const uint32_t sb = smem_u32(sm);
    const int tid = threadIdx.x, lane = tid & 31, wid = tid >> 5;
    const int row0 = blockIdx.x * 64;

    // W^T hi/lo -> smem (128 rows x 256B, xor-swizzled)
#pragma unroll
    for (int c = 0; c < 8; c++) {
        int idx = tid + 256 * c;
        int r = idx >> 4, col = idx & 15;
        uint32_t sw = (uint32_t)(r * 256 + ((col * 16) ^ ((r & 7) << 4)));
        cp_async16(sb + A_BH + sw, g_WTH + r * 128 + col * 8);
        cp_async16(sb + A_BL + sw, g_WTL + r * 128 + col * 8);
    }
    asm volatile("cp.async.commit_group;" ::: "memory");

    // h tile (64 x 128 f32) -> hi/lo fp16 smem
#pragma unroll
    for (int c = 0; c < 8; c++) {
        int idx = tid + 256 * c;
        int r = idx >> 5, fq = idx & 31;
        float4 w = *(const float4*)(h + (size_t)(row0 + r) * 128 + fq * 4);
        __half h0 = __float2half_rn(w.x), h1 = __float2half_rn(w.y);
        __half h2 = __float2half_rn(w.z), h3 = __float2half_rn(w.w);
        float l0 = w.x - __half2float(h0), l1 = w.y - __half2float(h1);
        float l2 = w.z - __half2float(h2), l3 = w.w - __half2float(h3);
        uint32_t sw = (uint32_t)(r * 256 + ((fq * 8) ^ ((r & 7) << 4)));
        __half2 hA = __halves2half2(h0, h1), hB = __halves2half2(h2, h3);
        *(uint2*)(sm + A_AH + sw) = make_uint2(*(uint32_t*)&hA, *(uint32_t*)&hB);
        *(uint2*)(sm + A_AL + sw) = make_uint2(pack_f16x2(l0, l1), pack_f16x2(l2, l3));
    }
    asm volatile("cp.async.wait_group 0;" ::: "memory");
    __syncthreads();

    const int warpM = wid >> 2, warpN = wid & 3;     // 2 x 4
    const int l15 = lane & 15, l16 = lane >> 4;
    const uint32_t xorv = (uint32_t)((l15 & 7) << 4);

    float acc[2][4][4];
#pragma unroll
    for (int mt = 0; mt < 2; mt++)
#pragma unroll
        for (int nt = 0; nt < 4; nt++)
#pragma unroll
            for (int e = 0; e < 4; e++) acc[mt][nt][e] = 0.f;

    uint32_t aRow[2];
#pragma unroll
    for (int mt = 0; mt < 2; mt++)
        aRow[mt] = (uint32_t)((warpM * 32 + mt * 16 + l15) * 256);
    uint32_t bCol[2];
#pragma unroll
    for (int ng = 0; ng < 2; ng++)
        bCol[ng] = ((uint32_t)((warpN * 32 + ng * 16 + l16 * 8) * 2)) ^ xorv;

#pragma unroll
    for (int kk = 0; kk < 8; kk++) {
        const uint32_t aCol = ((uint32_t)(kk * 32 + l16 * 16)) ^ xorv;
        uint32_t aH[2][4], aL[2][4];
#pragma unroll
        for (int mt = 0; mt < 2; mt++) {
            ldsm_x4(aH[mt][0], aH[mt][1], aH[mt][2], aH[mt][3], sb + A_AH + aRow[mt] + aCol);
            ldsm_x4(aL[mt][0], aL[mt][1], aL[mt][2], aL[mt][3], sb + A_AL + aRow[mt] + aCol);
        }
        const uint32_t bRow = (uint32_t)((kk * 16 + l15) * 256);
        uint32_t bH[2][4], bL[2][4];
#pragma unroll
        for (int ng = 0; ng < 2; ng++) {
            ldsm_x4t(bH[ng][0], bH[ng][1], bH[ng][2], bH[ng][3], sb + A_BH + bRow + bCol[ng]);
            ldsm_x4t(bL[ng][0], bL[ng][1], bL[ng][2], bL[ng][3], sb + A_BL + bRow + bCol[ng]);
        }
#pragma unroll
        for (int mt = 0; mt < 2; mt++)
#pragma unroll
            for (int nt = 0; nt < 4; nt++) {
                const int g = nt >> 1, hh = (nt & 1) * 2;
                mma16816(acc[mt][nt], aH[mt], bH[g][hh], bH[g][hh + 1]);
                mma16816(acc[mt][nt], aH[mt], bL[g][hh], bL[g][hh + 1]);
                mma16816(acc[mt][nt], aL[mt], bH[g][hh], bH[g][hh + 1]);
            }
    }

    // store Wh fp16 rn
#pragma unroll
    for (int mt = 0; mt < 2; mt++) {
        const int r0 = row0 + warpM * 32 + mt * 16 + (lane >> 2);
        const int r1 = r0 + 8;
#pragma unroll
        for (int nt = 0; nt < 4; nt++) {
            const int c0 = warpN * 32 + nt * 8 + (lane & 3) * 2;
            __half h0 = __float2half_rn(acc[mt][nt][0]), h1 = __float2half_rn(acc[mt][nt][1]);
            __half h2 = __float2half_rn(acc[mt][nt][2]), h3 = __float2half_rn(acc[mt][nt][3]);
            __half2 p0 = __halves2half2(h0, h1), p1 = __halves2half2(h2, h3);
            *(uint32_t*)(g_BH + (size_t)r0 * 128 + c0) = *(uint32_t*)&p0;
            *(uint32_t*)(g_BH + (size_t)r1 * 128 + c0) = *(uint32_t*)&p1;
        }
    }

    // s,t from exact accumulators
    float ps[2][2] = {{0.f,0.f},{0.f,0.f}}, pt[2][2] = {{0.f,0.f},{0.f,0.f}};
#pragma unroll
    for (int mt = 0; mt < 2; mt++)
#pragma unroll
        for (int nt = 0; nt < 4; nt++) {
            const int c0 = warpN * 32 + nt * 8 + (lane & 3) * 2;
            float2 av = *(const float2*)(a + c0);
            float2 dv = *(const float2*)(a + 128 + c0);
            ps[mt][0] += acc[mt][nt][0] * av.x + acc[mt][nt][1] * av.y;
            ps[mt][1] += acc[mt][nt][2] * av.x + acc[mt][nt][3] * av.y;
            pt[mt][0] += acc[mt][nt][0] * dv.x + acc[mt][nt][1] * dv.y;
            pt[mt][1] += acc[mt][nt][2] * dv.x + acc[mt][nt][3] * dv.y;
        }
#pragma unroll
    for (int o = 1; o < 4; o <<= 1) {
#pragma unroll
        for (int mt = 0; mt < 2; mt++) {
            ps[mt][0] += __shfl_xor_sync(0xFFFFFFFFu, ps[mt][0], o);
            ps[mt][1] += __shfl_xor_sync(0xFFFFFFFFu, ps[mt][1], o);
            pt[mt][0] += __shfl_xor_sync(0xFFFFFFFFu, pt[mt][0], o);
            pt[mt][1] += __shfl_xor_sync(0xFFFFFFFFu, pt[mt][1], o);
        }
    }
    float* sredS = (float*)(sm + A_SRED);
    float* sredT = (float*)(sm + A_SRED + 1024);
    if ((lane & 3) == 0) {
#pragma unroll
        for (int mt = 0; mt < 2; mt++) {
            int rl = warpM * 32 + mt * 16 + (lane >> 2);
            sredS[rl * 4 + warpN] = ps[mt][0];
            sredS[(rl + 8) * 4 + warpN] = ps[mt][1];
            sredT[rl * 4 + warpN] = pt[mt][0];
            sredT[(rl + 8) * 4 + warpN] = pt[mt][1];
        }
    }
    __syncthreads();
    if (tid < 64) {
        float s = sredS[tid*4] + sredS[tid*4+1] + sredS[tid*4+2] + sredS[tid*4+3];
        float t = sredT[tid*4] + sredT[tid*4+1] + sredT[tid*4+2] + sredT[tid*4+3];
        int row = row0 + tid;
        g_u[row] = __expf(s);   g_p[row] = __expf(0.2f * s);
        g_v[row] = __expf(t);   g_q[row] = __expf(0.2f * t);
    }
}

// ---------------------------------------------------------------------------
// K4: fused. M-tile 64, TK=128 (16 tiles), v/q in smem, adj gmem->regs,
//     B double-buffered, P construct split across kk==0/2.
// ---------------------------------------------------------------------------
#define TK 128
#define F_P(b)  ((b) * 16384)             // P  64x128 fp16 (256B rows)
#define F_B(b)  (32768 + (b) * 32768)     // Wh 128x128 fp16 (256B rows)
#define F_V     98304                      // v[2048] f32
#define F_Q     106496                     // q[2048] f32
#define F_ZR    114688
#define F_ZI    114944
#define F_SMEM  115200

__global__ void __launch_bounds__(256, 2) gat_fused(
    const int* __restrict__ adj, float* __restrict__ out)
{
    extern __shared__ char sm[];
    const uint32_t sb = smem_u32(sm);
    const int tid = threadIdx.x, lane = tid & 31, wid = tid >> 5;
    const int b = blockIdx.x, i0 = blockIdx.y * 64;
    const int tx = tid & 15, ty = tid >> 4;

    const int* adjB = adj + ((size_t)(b * NNODE + i0)) * NNODE;
    const __half* BHg = g_BH + (size_t)b * NNODE * DIM;

    float u_r[4], p_r[4];
    const int* adjRow[4];
#pragma unroll
    for (int m = 0; m < 4; m++) {
        int il = ty + 16 * m;
        u_r[m] = g_u[b * NNODE + i0 + il];
        p_r[m] = g_p[b * NNODE + i0 + il];
        adjRow[m] = adjB + (size_t)il * NNODE + 4 * tx;
    }

    // prologue: v,q and B(0) via cp.async
#pragma unroll
    for (int c = 0; c < 2; c++) {
        int idx = tid + 256 * c;
        cp_async16(sb + F_V + idx * 16, g_v + b * NNODE + idx * 4);
        cp_async16(sb + F_Q + idx * 16, g_q + b * NNODE + idx * 4);
    }
#pragma unroll
    for (int c = 0; c < 8; c++) {
        int idx = tid + 256 * c;
        int row = idx >> 4, col = idx & 15;
        uint32_t sw = (uint32_t)(row * 256 + ((col * 16) ^ ((row & 7) << 4)));
        cp_async16(sb + F_B(0) + sw, BHg + (size_t)row * DIM + col * 8);
    }
    asm volatile("cp.async.commit_group;" ::: "memory");
    asm volatile("cp.async.wait_group 0;" ::: "memory");
    __syncthreads();

    float zacc[4] = {0.f, 0.f, 0.f, 0.f};

    // construct P(0) (both halves), adj direct
#pragma unroll
    for (int hf = 0; hf < 2; hf++) {
        int jn = hf * 64 + 4 * tx;
        float4 v4 = *(const float4*)(sm + F_V + jn * 4);
        float4 q4 = *(const float4*)(sm + F_Q + jn * 4);
#pragma unroll
        for (int m = 0; m < 4; m++) {
            const int row = ty + 16 * m;
            int4 a4 = *(const int4*)(adjRow[m] + hf * 64);
            const float u = u_r[m], p = p_r[m];
            uint32_t w0 = __float_as_uint(fmaxf(u * v4.x, p * q4.x)) & (uint32_t)(-a4.x);
            uint32_t w1 = __float_as_uint(fmaxf(u * v4.y, p * q4.y)) & (uint32_t)(-a4.y);
            uint32_t w2 = __float_as_uint(fmaxf(u * v4.z, p * q4.z)) & (uint32_t)(-a4.z);
            uint32_t w3 = __float_as_uint(fmaxf(u * v4.w, p * q4.w)) & (uint32_t)(-a4.w);
            float f0 = __uint_as_float(w0), f1 = __uint_as_float(w1);
            float f2 = __uint_as_float(w2), f3 = __uint_as_float(w3);
            zacc[m] += (f0 + f1) + (f2 + f3);
            uint32_t off = (uint32_t)(row * 256 + ((hf * 128 + tx * 8) ^ ((row & 7) << 4)));
            *(uint2*)(sm + F_P(0) + off) = make_uint2(pack_f16x2(f0, f1), pack_f16x2(f2, f3));
        }
    }

    // adj(1) prefetch
    int4 aN[8];
#pragma unroll
    for (int hf = 0; hf < 2; hf++)
#pragma unroll
        for (int m = 0; m < 4; m++)
            aN[hf * 4 + m] = *(const int4*)(adjRow[m] + TK + hf * 64);

    __syncthreads();

    float acc[2][4][4];
#pragma unroll
    for (int mt = 0; mt < 2; mt++)
#pragma unroll
        for (int nt = 0; nt < 4; nt++)
#pragma unroll
            for (int e = 0; e < 4; e++) acc[mt][nt][e] = 0.f;

    const int warpM = wid >> 2, warpN = wid & 3;
    const int l15 = lane & 15, l16 = lane >> 4;
    const uint32_t xorv = (uint32_t)((l15 & 7) << 4);
    uint32_t aRow[2];
#pragma unroll
    for (int mt = 0; mt < 2; mt++)
        aRow[mt] = (uint32_t)((warpM * 32 + mt * 16 + l15) * 256);
    uint32_t bCol[2];
#pragma unroll
    for (int ng = 0; ng < 2; ng++)
        bCol[ng] = ((uint32_t)((warpN * 32 + ng * 16 + l16 * 8) * 2)) ^ xorv;

    for (int kt = 0; kt < NNODE / TK; ++kt) {
        const int cb = kt & 1, pb = cb ^ 1;

        if (kt < 15) {
            const int j1 = (kt + 1) * TK;
#pragma unroll
            for (int c = 0; c < 8; c++) {
                int idx = tid + 256 * c;
                int row = idx >> 4, col = idx & 15;
                uint32_t sw = (uint32_t)(row * 256 + ((col * 16) ^ ((row & 7) << 4)));
                cp_async16(sb + F_B(pb) + sw, BHg + (size_t)(j1 + row) * DIM + col * 8);
            }
        }
        asm volatile("cp.async.commit_group;" ::: "memory");

        const uint32_t Pb = sb + F_P(cb), Bb = sb + F_B(cb);
#pragma unroll
        for (int kk = 0; kk < 8; ++kk) {
            const uint32_t aCol = ((uint32_t)(kk * 32 + l16 * 16)) ^ xorv;
            uint32_t aH[2][4];
#pragma unroll
            for (int mt = 0; mt < 2; mt++)
                ldsm_x4(aH[mt][0], aH[mt][1], aH[mt][2], aH[mt][3], Pb + aRow[mt] + aCol);
            const uint32_t bRow = (uint32_t)((kk * 16 + l15) * 256);
            uint32_t bH[2][4];
#pragma unroll
            for (int ng = 0; ng < 2; ng++)
                ldsm_x4t(bH[ng][0], bH[ng][1], bH[ng][2], bH[ng][3], Bb + bRow + bCol[ng]);
#pragma unroll
            for (int mt = 0; mt < 2; mt++)
#pragma unroll
                for (int nt = 0; nt < 4; nt++) {
                    const int g = nt >> 1, hh = (nt & 1) * 2;
                    mma16816(acc[mt][nt], aH[mt], bH[g][hh], bH[g][hh + 1]);
                }

            if ((kk == 0 || kk == 2) && kt < 15) {
                // construct half of P(kt+1)
                const int hf = kk >> 1;
                int jn = (kt + 1) * TK + hf * 64 + 4 * tx;
                float4 v4 = *(const float4*)(sm + F_V + jn * 4);
                float4 q4 = *(const float4*)(sm + F_Q + jn * 4);
                char* P = sm + F_P(pb);
#pragma unroll
                for (int m = 0; m < 4; m++) {
                    const int row = ty + 16 * m;
                    const int4 a4 = aN[hf * 4 + m];
                    const float u = u_r[m], p = p_r[m];
                    uint32_t w0 = __float_as_uint(fmaxf(u * v4.x, p * q4.x)) & (uint32_t)(-a4.x);
                    uint32_t w1 = __float_as_uint(fmaxf(u * v4.y, p * q4.y)) & (uint32_t)(-a4.y);
                    uint32_t w2 = __float_as_uint(fmaxf(u * v4.z, p * q4.z)) & (uint32_t)(-a4.z);
                    uint32_t w3 = __float_as_uint(fmaxf(u * v4.w, p * q4.w)) & (uint32_t)(-a4.w);
                    float f0 = __uint_as_float(w0), f1 = __uint_as_float(w1);
                    float f2 = __uint_as_float(w2), f3 = __uint_as_float(w3);
                    zacc[m] += (f0 + f1) + (f2 + f3);
                    uint32_t off = (uint32_t)(row * 256 + ((hf * 128 + tx * 8) ^ ((row & 7) << 4)));
                    *(uint2*)(P + off) = make_uint2(pack_f16x2(f0, f1), pack_f16x2(f2, f3));
                }
            }
            if ((kk == 4 || kk == 6) && kt < 14) {
                // prefetch adj(kt+2) half into regs
                const int hf = (kk - 4) >> 1;
                const int j2 = (kt + 2) * TK + hf * 64;
#pragma unroll
                for (int m = 0; m < 4; m++)
                    aN[hf * 4 + m] = *(const int4*)(adjRow[m] + j2);
            }
        }
        asm volatile("cp.async.wait_group 0;" ::: "memory");
        __syncthreads();
    }

    // Z reduction and normalize
    float* zr = (float*)(sm + F_ZR);
    float* zi = (float*)(sm + F_ZI);
#pragma unroll
    for (int m = 0; m < 4; m++) {
        float z = zacc[m];
#pragma unroll
        for (int o = 1; o < 16; o <<= 1)
            z += __shfl_xor_sync(0xFFFFFFFFu, z, o);
        if (tx == 0) zr[ty + 16 * m] = z;
    }
    __syncthreads();
    if (tid < 64) {
        float z = zr[tid];
        zi[tid] = (z > 0.f) ? (1.f / z) : 0.f;
    }
    __syncthreads();

    float* outB = out + ((size_t)(b * NNODE + i0)) * DIM;
#pragma unroll
    for (int mt = 0; mt < 2; mt++) {
        const int r0 = warpM * 32 + mt * 16 + (lane >> 2);
        const int r1 = r0 + 8;
        const float z0 = zi[r0], z1 = zi[r1];
#pragma unroll
        for (int nt = 0; nt < 4; nt++) {
            const int c0 = warpN * 32 + nt * 8 + (lane & 3) * 2;
            *(float2*)(outB + (size_t)r0 * DIM + c0) =
                make_float2(acc[mt][nt][0] * z0, acc[mt][nt][1] * z0);
            *(float2*)(outB + (size_t)r1 * DIM + c0) =
                make_float2(acc[mt][nt][2] * z1, acc[mt][nt][3] * z1);
        }
    }
}

// ---------------------------------------------------------------------------
extern "C" void kernel_launch(void* const* d_in, const int* in_sizes, int n_in,
                              void* d_out, int out_size)
{
    const float* h   = (const float*)d_in[0];
    const int*   adj = (const int*)  d_in[1];
    const float* W   = (const float*)d_in[2];
    const float* a   = (const float*)d_in[3];
    float*       out = (float*)d_out;

    static int attr_set = 0;
    if (!attr_set) {
        cudaFuncSetAttribute(gat_wh_st, cudaFuncAttributeMaxDynamicSharedMemorySize, A_SMEM);
        cudaFuncSetAttribute(gat_fused, cudaFuncAttributeMaxDynamicSharedMemorySize, F_SMEM);
        attr_set = 1;
    }

    gat_wprep<<<64, 256>>>(W);
    gat_wh_st<<<NROWS / 64, 256, A_SMEM>>>(h, a);
    gat_fused<<<dim3(BATCH, NNODE / 64), 256, F_SMEM>>>(adj, out);
}